// round 6
// baseline (speedup 1.0000x reference)
#include <cuda_runtime.h>
#include <cuda_bf16.h>
#include <cstdint>

#define D_MODEL 2048
#define SEQ     2048
#define BATCH   2
#define NHEADS  16
#define HDIM    128
#define M_TOK   (BATCH*SEQ)   // 4096

#if defined(__CUDA_ARCH_FEAT_SM103_ALL) || defined(__CUDA_ARCH_FEAT_SM100_ALL) || \
    (defined(__CUDA_ARCH_SPECIFIC__) && (__CUDA_ARCH_SPECIFIC__ >= 1000))
#define HAS_TCGEN05 1
#else
#define HAS_TCGEN05 0
#endif

// ---- persistent scratch (packed bf16 hi/lo operands only; no fp32 intermediates) ----
__device__ __nv_bfloat16 g_xh[M_TOK * D_MODEL];
__device__ __nv_bfloat16 g_xl[M_TOK * D_MODEL];
__device__ __nv_bfloat16 g_chh[M_TOK * D_MODEL];
__device__ __nv_bfloat16 g_cll[M_TOK * D_MODEL];
__device__ __nv_bfloat16 g_wh[4][D_MODEL * D_MODEL];
__device__ __nv_bfloat16 g_wl[4][D_MODEL * D_MODEL];

__device__ __nv_bfloat16 g_aqh[M_TOK * D_MODEL];   // Q tiles: [bh][rt16][2ch x 16KB]
__device__ __nv_bfloat16 g_aql[M_TOK * D_MODEL];
__device__ __nv_bfloat16 g_akh[M_TOK * D_MODEL];   // K tiles: [bh][kt32][2ch x 8KB]
__device__ __nv_bfloat16 g_akl[M_TOK * D_MODEL];
__device__ __nv_bfloat16 g_avh[M_TOK * D_MODEL];   // V^T tiles: [bh][kt32][16KB]
__device__ __nv_bfloat16 g_avl[M_TOK * D_MODEL];

// ============================================================
// PTX helpers
// ============================================================
__device__ __forceinline__ uint32_t smem_u32(const void* p) {
    uint32_t a;
    asm("{ .reg .u64 t; cvta.to.shared.u64 t, %1; cvt.u32.u64 %0, t; }" : "=r"(a) : "l"(p));
    return a;
}
__device__ __forceinline__ uint32_t elect_one_pred() {
    uint32_t p;
    asm volatile("{ .reg .pred p; elect.sync _|p, 0xFFFFFFFF; selp.b32 %0, 1, 0, p; }" : "=r"(p));
    return p;
}
__device__ __forceinline__ uint32_t cluster_rank() {
    uint32_t r;
    asm("mov.u32 %0, %%cluster_ctarank;" : "=r"(r));
    return r;
}
static constexpr uint64_t SMEM_DESC_BASE_SW128 =
    (uint64_t(2) << 61) | (uint64_t(1) << 46) | (uint64_t(64) << 32) | (uint64_t(1) << 16);
#define MAKE_SMEM_DESC(base_addr) \
    (SMEM_DESC_BASE_SW128 | ((uint64_t)((base_addr) >> 4) & 0x3FFF))
#define SMEM_SWIZZLE_128B(off) ((off) ^ (((off) >> 3) & 0x70))

#define MBARRIER_INIT(mbar, count) \
    asm volatile("mbarrier.init.shared.b64 [%0], %1;" \
                 :: "r"((uint32_t)(mbar)), "r"((uint32_t)(count)) : "memory")
#define MBARRIER_INVAL(mbar) \
    asm volatile("mbarrier.inval.shared.b64 [%0];" :: "r"((uint32_t)(mbar)) : "memory")
#define MBARRIER_EXPECT_TX(mbar, bytes) \
    asm volatile("mbarrier.arrive.expect_tx.shared.b64 _, [%0], %1;" \
                 :: "r"((uint32_t)(mbar)), "r"((uint32_t)(bytes)) : "memory")
#define MBARRIER_ARRIVE(mbar) \
    asm volatile("mbarrier.arrive.shared.b64 _, [%0];" :: "r"((uint32_t)(mbar)) : "memory")
#define MBARRIER_ARRIVE_CLUSTER(mbar, rank) \
    asm volatile("{ .reg .b32 ra; mapa.shared::cluster.u32 ra, %0, %1; " \
                 "mbarrier.arrive.shared::cluster.b64 _, [ra]; }" \
                 :: "r"((uint32_t)(mbar)), "r"((uint32_t)(rank)) : "memory")
#define MBARRIER_WAIT_PARITY(mbar, parity) do {                                          \
    uint32_t _m = (uint32_t)(mbar);                                                      \
    uint32_t _p = (uint32_t)(parity);                                                    \
    uint32_t _done;                                                                      \
    asm volatile("{ .reg .pred p; mbarrier.try_wait.parity.acquire.cta.shared::cta.b64 " \
                 "p, [%1], %2; selp.b32 %0, 1, 0, p; }"                                  \
                 : "=r"(_done) : "r"(_m), "r"(_p) : "memory");                           \
    if (!_done) {                                                                        \
        asm volatile("{ .reg .pred P1; WL_%=: "                                          \
                     "mbarrier.try_wait.parity.acquire.cta.shared::cta.b64 P1, [%0], %1, 0x989680; " \
                     "@P1 bra.uni WD_%=; bra.uni WL_%=; WD_%=: }"                        \
                     :: "r"(_m), "r"(_p) : "memory");                                    \
    }                                                                                    \
} while (0)

#define CLUSTER_SYNC() do { \
    asm volatile("barrier.cluster.arrive.aligned;" ::: "memory"); \
    asm volatile("barrier.cluster.wait.aligned;" ::: "memory"); \
} while (0)

#define BULK_CP(dst_smem, src_gmem, bytes, mbar) \
    asm volatile("cp.async.bulk.shared::cluster.global.mbarrier::complete_tx::bytes " \
                 "[%0], [%1], %2, [%3];" \
                 :: "r"((uint32_t)(dst_smem)), "l"(src_gmem), "r"((uint32_t)(bytes)), \
                    "r"((uint32_t)(mbar)) : "memory")
#define BULK_CP_MC(dst_smem, src_gmem, bytes, mbar, mask) \
    asm volatile("cp.async.bulk.shared::cluster.global.mbarrier::complete_tx::bytes" \
                 ".multicast::cluster [%0], [%1], %2, [%3], %4;" \
                 :: "r"((uint32_t)(dst_smem)), "l"(src_gmem), "r"((uint32_t)(bytes)), \
                    "r"((uint32_t)(mbar)), "h"((uint16_t)(mask)) : "memory")

#if HAS_TCGEN05
#define TCGEN05_ALLOC(smem_addr, nCols) \
    asm volatile("tcgen05.alloc.cta_group::1.sync.aligned.shared::cta.b32 [%0], %1;" \
                 :: "r"((uint32_t)(smem_addr)), "r"((uint32_t)(nCols)) : "memory")
#define TCGEN05_DEALLOC(tmem_addr, nCols) \
    asm volatile("tcgen05.dealloc.cta_group::1.sync.aligned.b32 %0, %1;" \
                 :: "r"(tmem_addr), "r"((uint32_t)(nCols)))
#define TCGEN05_RELINQUISH() \
    asm volatile("tcgen05.relinquish_alloc_permit.cta_group::1.sync.aligned;")
#define TCGEN05_COMMIT(mbar) \
    asm volatile("tcgen05.commit.cta_group::1.mbarrier::arrive::one.shared::cluster.b64 [%0];" \
                 :: "r"((uint32_t)(mbar)) : "memory")
#define TCGEN05_FENCE_AFTER() \
    asm volatile("tcgen05.fence::after_thread_sync;" ::: "memory")
#define TCGEN05_FENCE_BEFORE() \
    asm volatile("tcgen05.fence::before_thread_sync;" ::: "memory")
#define TCGEN05_WAIT_LD() \
    asm volatile("tcgen05.wait::ld.sync.aligned;" ::: "memory")
#define TCGEN05_WAIT_ST() \
    asm volatile("tcgen05.wait::st.sync.aligned;" ::: "memory")

#define TCGEN05_LD_32X32B_X32(r, tmem_addr) \
    asm volatile( \
        "tcgen05.ld.sync.aligned.32x32b.x32.b32 " \
        "{%0, %1, %2, %3, %4, %5, %6, %7, " \
        " %8, %9, %10, %11, %12, %13, %14, %15, " \
        " %16, %17, %18, %19, %20, %21, %22, %23, " \
        " %24, %25, %26, %27, %28, %29, %30, %31}, [%32];" \
        : "=r"((r)[0]),  "=r"((r)[1]),  "=r"((r)[2]),  "=r"((r)[3]), \
          "=r"((r)[4]),  "=r"((r)[5]),  "=r"((r)[6]),  "=r"((r)[7]), \
          "=r"((r)[8]),  "=r"((r)[9]),  "=r"((r)[10]), "=r"((r)[11]), \
          "=r"((r)[12]), "=r"((r)[13]), "=r"((r)[14]), "=r"((r)[15]), \
          "=r"((r)[16]), "=r"((r)[17]), "=r"((r)[18]), "=r"((r)[19]), \
          "=r"((r)[20]), "=r"((r)[21]), "=r"((r)[22]), "=r"((r)[23]), \
          "=r"((r)[24]), "=r"((r)[25]), "=r"((r)[26]), "=r"((r)[27]), \
          "=r"((r)[28]), "=r"((r)[29]), "=r"((r)[30]), "=r"((r)[31]) \
        : "r"(tmem_addr))

#define TCGEN05_ST_32X32B_X32(tmem_addr, r) \
    asm volatile( \
        "tcgen05.st.sync.aligned.32x32b.x32.b32 [%0], " \
        "{%1, %2, %3, %4, %5, %6, %7, %8, " \
        " %9, %10, %11, %12, %13, %14, %15, %16, " \
        " %17, %18, %19, %20, %21, %22, %23, %24, " \
        " %25, %26, %27, %28, %29, %30, %31, %32};" \
        :: "r"(tmem_addr), \
           "r"((r)[0]),  "r"((r)[1]),  "r"((r)[2]),  "r"((r)[3]), \
           "r"((r)[4]),  "r"((r)[5]),  "r"((r)[6]),  "r"((r)[7]), \
           "r"((r)[8]),  "r"((r)[9]),  "r"((r)[10]), "r"((r)[11]), \
           "r"((r)[12]), "r"((r)[13]), "r"((r)[14]), "r"((r)[15]), \
           "r"((r)[16]), "r"((r)[17]), "r"((r)[18]), "r"((r)[19]), \
           "r"((r)[20]), "r"((r)[21]), "r"((r)[22]), "r"((r)[23]), \
           "r"((r)[24]), "r"((r)[25]), "r"((r)[26]), "r"((r)[27]), \
           "r"((r)[28]), "r"((r)[29]), "r"((r)[30]), "r"((r)[31]) \
        : "memory")

__device__ __forceinline__ void mma_f16_ss(uint32_t d_tmem, uint64_t a_desc, uint64_t b_desc,
                                           uint32_t idesc, uint32_t enable) {
    asm volatile(
        "{\n\t"
        ".reg .pred p;\n\t"
        "setp.ne.u32 p, %4, 0;\n\t"
        "tcgen05.mma.cta_group::1.kind::f16 [%0], %1, %2, %3, {%5, %5, %5, %5}, p;\n\t"
        "}"
        :: "r"(d_tmem), "l"(a_desc), "l"(b_desc), "r"(idesc), "r"(enable), "r"(0u)
        : "memory");
}
__device__ __forceinline__ void mma_f16_ts(uint32_t d_tmem, uint32_t a_tmem, uint64_t b_desc,
                                           uint32_t idesc, uint32_t enable) {
    asm volatile(
        "{\n\t"
        ".reg .pred p;\n\t"
        "setp.ne.u32 p, %4, 0;\n\t"
        "tcgen05.mma.cta_group::1.kind::f16 [%0], [%1], %2, %3, {%5, %5, %5, %5}, p;\n\t"
        "}"
        :: "r"(d_tmem), "r"(a_tmem), "l"(b_desc), "r"(idesc), "r"(enable), "r"(0u)
        : "memory");
}
#endif  // HAS_TCGEN05

__device__ __forceinline__ void split_bf16(float f, __nv_bfloat16& h, __nv_bfloat16& l) {
    h = __float2bfloat16(f);
    l = __float2bfloat16(f - __bfloat162float(h));
}

// ============================================================
// fp32 -> bf16 hi/lo split + GEMM tile packing (inputs x, W)
// ============================================================
__global__ __launch_bounds__(256) void split_pack(
    const float* __restrict__ src, __nv_bfloat16* __restrict__ hi,
    __nv_bfloat16* __restrict__ lo, int nrt, int n8)
{
    int i = blockIdx.x * blockDim.x + threadIdx.x;
    if (i >= n8) return;
    int elem = i * 8;
    int row = elem >> 11;
    int col = elem & 2047;
    int rt = row >> 7, r = row & 127;
    int c  = col >> 6, kc = col & 63;
    size_t tb = ((size_t)(c * nrt + rt)) << 14;
    uint32_t so = SMEM_SWIZZLE_128B((uint32_t)(r * 128 + kc * 2));

    float4 v0 = ((const float4*)src)[i * 2];
    float4 v1 = ((const float4*)src)[i * 2 + 1];
    float f[8] = {v0.x, v0.y, v0.z, v0.w, v1.x, v1.y, v1.z, v1.w};
    __align__(16) __nv_bfloat16 h[8], l[8];
#pragma unroll
    for (int j = 0; j < 8; j++) split_bf16(f[j], h[j], l[j]);
    *(uint4*)((char*)hi + tb + so) = *(uint4*)h;
    *(uint4*)((char*)lo + tb + so) = *(uint4*)l;
}

// ============================================================
// Fused tcgen05 GEMM, 2-CTA cluster (B multicast).
// mode 0/1/2 = Q/K/V projection (epilogue packs attention operands)
// mode 3     = O projection (epilogue writes fp32 out)
// Tile 128(M) x 256(N), K-chunk 64 bf16, 3-MMA hi/lo split.
// ============================================================
#define NCH  32
#define NRT_A 32
#define NRT_W 16
#define TIL  16384
#define STG  (6 * TIL)
#define SMB0 1024
#define GEMM_SMEM (SMB0 + 2 * STG)
#define GEMM_IDESC 0x8400490u
// barriers: full@64+16s, cbar@96+16s, free@128+16s(count2)

__global__ __launch_bounds__(256) __cluster_dims__(1, 2, 1) void gemm_fused(
    int mode_base, const float* __restrict__ b0, const float* __restrict__ b1,
    const float* __restrict__ b2, const float* __restrict__ b3,
    float* __restrict__ out)
{
#if HAS_TCGEN05
    extern __shared__ char sm[];
    const uint32_t smb = smem_u32(sm);
    const int tid = threadIdx.x;
    const int wid = tid >> 5;
    const int lid = tid & 31;
    const int rm = blockIdx.y;
    const int bx = blockIdx.x;
    const int mode = mode_base + blockIdx.z;
    const uint32_t rank = cluster_rank();

    const __nv_bfloat16* Ah = (mode < 3) ? g_xh : g_chh;
    const __nv_bfloat16* Al = (mode < 3) ? g_xl : g_cll;
    const __nv_bfloat16* Bh = g_wh[mode];
    const __nv_bfloat16* Bl = g_wl[mode];
    const float* bias = (mode == 0) ? b0 : (mode == 1) ? b1 : (mode == 2) ? b2 : b3;
    const float alpha = (mode == 0) ? 0.08838834764831845f : 1.0f;

    if (wid == 0) TCGEN05_ALLOC(smb + 0, 256);
    if (tid == 0) {
#pragma unroll
        for (int s = 0; s < 2; ++s) {
            MBARRIER_INIT(smb + 64 + 16 * s, 1);    // full
            MBARRIER_INIT(smb + 96 + 16 * s, 1);    // mma commit
            MBARRIER_INIT(smb + 128 + 16 * s, 2);   // stage free (cluster)
        }
    }
    __syncthreads();
    CLUSTER_SYNC();

    uint32_t tmem;
    asm volatile("ld.shared.b32 %0, [%1];" : "=r"(tmem) : "r"(smb + 0));

    if (wid == 0 && elect_one_pred()) {
#define LOAD_CHUNK(c, s)                                                        \
        do {                                                                    \
            uint32_t st = smb + SMB0 + (s) * STG;                               \
            uint32_t fb = smb + 64 + 16 * (s);                                  \
            size_t ao = ((size_t)((c) * NRT_A + rm)) << 14;                     \
            size_t bo = ((size_t)((c) * NRT_W + 2 * bx)) << 14;                 \
            MBARRIER_EXPECT_TX(fb, 6 * TIL);                                    \
            BULK_CP(st,       (const char*)Ah + ao, TIL, fb);                   \
            BULK_CP(st + TIL, (const char*)Al + ao, TIL, fb);                   \
            if (rank == 0) BULK_CP_MC(st + 2 * TIL, (const char*)Bh + bo, 2 * TIL, fb, 3); \
            else           BULK_CP_MC(st + 4 * TIL, (const char*)Bl + bo, 2 * TIL, fb, 3); \
        } while (0)

        LOAD_CHUNK(0, 0);
        LOAD_CHUNK(1, 1);

        for (int c = 0; c < NCH; ++c) {
            int s = c & 1, ph = (c >> 1) & 1;
            uint32_t st = smb + SMB0 + s * STG;
            MBARRIER_WAIT_PARITY(smb + 64 + 16 * s, ph);
            uint64_t dAh = MAKE_SMEM_DESC(st);
            uint64_t dAl = MAKE_SMEM_DESC(st + TIL);
            uint64_t dBh = MAKE_SMEM_DESC(st + 2 * TIL);
            uint64_t dBl = MAKE_SMEM_DESC(st + 4 * TIL);
#pragma unroll
            for (int ks = 0; ks < 4; ++ks) {
                mma_f16_ss(tmem, dAh + ks * 2, dBh + ks * 2, GEMM_IDESC, (c | ks) != 0);
                mma_f16_ss(tmem, dAl + ks * 2, dBh + ks * 2, GEMM_IDESC, 1);
                mma_f16_ss(tmem, dAh + ks * 2, dBl + ks * 2, GEMM_IDESC, 1);
            }
            TCGEN05_COMMIT(smb + 96 + 16 * s);
            MBARRIER_WAIT_PARITY(smb + 96 + 16 * s, ph);
            if (c + 2 < NCH) {
                MBARRIER_ARRIVE_CLUSTER(smb + 128 + 16 * s, 0);
                MBARRIER_ARRIVE_CLUSTER(smb + 128 + 16 * s, 1);
                MBARRIER_WAIT_PARITY(smb + 128 + 16 * s, ph);
                LOAD_CHUNK(c + 2, s);
            }
        }
#undef LOAD_CHUNK
    }
    __syncthreads();
    TCGEN05_FENCE_AFTER();

    // epilogue: wg = col half (one head for modes<3), sub = row group
    const int wg = wid >> 2;
    const int sub = wid & 3;
    const int m = blockIdx.y * 128 + sub * 32 + lid;     // global token / row
    const int hd = bx * 2 + wg;                          // head (modes<3)
    const int b_ = m >> 11, s_ = m & 2047;
    const int bh2 = b_ * 16 + hd;
    __align__(16) __nv_bfloat16 hv[8], lv[8];

#pragma unroll
    for (int cb = 0; cb < 4; ++cb) {
        uint32_t r[32];
        TCGEN05_LD_32X32B_X32(r, tmem + wg * 128 + cb * 32);
        TCGEN05_WAIT_LD();
        int n0 = bx * 256 + wg * 128 + cb * 32;

        if (mode == 3) {
            float* crow = out + (size_t)m * D_MODEL;
#pragma unroll
            for (int j = 0; j < 32; j += 4) {
                float4 o;
                o.x = __uint_as_float(r[j + 0]) + bias[n0 + j + 0];
                o.y = __uint_as_float(r[j + 1]) + bias[n0 + j + 1];
                o.z = __uint_as_float(r[j + 2]) + bias[n0 + j + 2];
                o.w = __uint_as_float(r[j + 3]) + bias[n0 + j + 3];
                *(float4*)(crow + n0 + j) = o;
            }
        } else if (mode == 2) {
            // V^T pack: tile (bh*32+kt), element (d, sc)
            int kt = s_ >> 6, sc = s_ & 63;
            size_t tb = ((size_t)(bh2 * 32 + kt)) << 14;
#pragma unroll
            for (int j = 0; j < 32; ++j) {
                float f = __uint_as_float(r[j]) + bias[n0 + j];
                __nv_bfloat16 h8, l8;
                split_bf16(f, h8, l8);
                int d = cb * 32 + j;
                uint32_t off = SMEM_SWIZZLE_128B((uint32_t)(d * 128 + sc * 2));
                *(__nv_bfloat16*)((char*)g_avh + tb + off) = h8;
                *(__nv_bfloat16*)((char*)g_avl + tb + off) = l8;
            }
        } else {
            size_t tb;
            uint32_t rr;
            char *dh, *dl;
            if (mode == 0) {
                int rt2 = s_ >> 7; rr = s_ & 127;
                tb = ((size_t)((bh2 * 16 + rt2) * 2 + (cb >> 1))) << 14;
                dh = (char*)g_aqh + tb; dl = (char*)g_aql + tb;
            } else {
                int kt = s_ >> 6; rr = s_ & 63;
                tb = ((size_t)((bh2 * 32 + kt) * 2 + (cb >> 1))) << 13;
                dh = (char*)g_akh + tb; dl = (char*)g_akl + tb;
            }
            int kcb = (cb & 1) * 32;
#pragma unroll
            for (int j0 = 0; j0 < 32; j0 += 8) {
#pragma unroll
                for (int j = 0; j < 8; ++j) {
                    float f = (__uint_as_float(r[j0 + j]) + bias[n0 + j0 + j]) * alpha;
                    split_bf16(f, hv[j], lv[j]);
                }
                uint32_t so = SMEM_SWIZZLE_128B((uint32_t)(rr * 128 + (kcb + j0) * 2));
                *(uint4*)(dh + so) = *(uint4*)hv;
                *(uint4*)(dl + so) = *(uint4*)lv;
            }
        }
    }
    TCGEN05_FENCE_BEFORE();

    __syncthreads();
    CLUSTER_SYNC();
    if (tid == 0) {
#pragma unroll
        for (int s = 0; s < 2; ++s) {
            MBARRIER_INVAL(smb + 64 + 16 * s);
            MBARRIER_INVAL(smb + 96 + 16 * s);
            MBARRIER_INVAL(smb + 128 + 16 * s);
        }
    }
    __syncthreads();
    if (wid == 0) {
        TCGEN05_RELINQUISH();
        TCGEN05_DEALLOC(tmem, 256);
    }
    CLUSTER_SYNC();
#endif
}

// ============================================================
// tcgen05 flash attention, 2-CTA cluster (KV multicast),
// no-max softmax, O accum in TMEM, packed-ctx epilogue.
// grid (16, 32) cluster (2,1,1), 160 threads.
// ============================================================
#define AOFF_Q    1024
#define AOFF_MADD 66560
#define AOFF_ST   74752
#define ASTG      65536
#define ATTN_SMEM 205824
#define IDESC_S   0x8100490u
#define IDESC_PV  0x8200490u
// barriers: full_kv@64+16s, s_full@96+16s, smax_free@128+16s,
//           p_ready@160+16s, pv_done@192+16s, kv_free@224+16s (count2, cluster)
// TMEM cols: S0=0, S1=64, O=128, P0h=256, P0l=288, P1h=320, P1l=352

__global__ __launch_bounds__(160) __cluster_dims__(2, 1, 1) void attn_tc(
    const float* __restrict__ mask)
{
#if HAS_TCGEN05
    extern __shared__ char sm[];
    const uint32_t smb = smem_u32(sm);
    const int tid = threadIdx.x;
    const int wid = tid >> 5;
    const int lid = tid & 31;
    const int rt = blockIdx.x;
    const int bh = blockIdx.y;
    const int b = bh >> 4;
    const uint32_t rank = cluster_rank();

    if (wid == 0) TCGEN05_ALLOC(smb + 0, 512);
    if (tid == 0) {
#pragma unroll
        for (int s = 0; s < 2; ++s) {
            MBARRIER_INIT(smb + 64 + 16 * s, 1);
            MBARRIER_INIT(smb + 96 + 16 * s, 1);
            MBARRIER_INIT(smb + 128 + 16 * s, 4);
            MBARRIER_INIT(smb + 160 + 16 * s, 4);
            MBARRIER_INIT(smb + 192 + 16 * s, 1);
            MBARRIER_INIT(smb + 224 + 16 * s, 2);
        }
    }
    for (int j = tid; j < SEQ; j += 160) {
        float mv = mask[b * SEQ + j];
        ((float*)(sm + AOFF_MADD))[j] = (1.0f - mv) * -1e30f;
    }
    __syncthreads();
    CLUSTER_SYNC();

    uint32_t tmem;
    asm volatile("ld.shared.b32 %0, [%1];" : "=r"(tmem) : "r"(smb + 0));

    if (wid == 4) {
        if (elect_one_pred()) {
#define LOADKV(i2, s2, mb)                                                  \
            do {                                                            \
                size_t kb = ((size_t)(bh * 32 + (i2))) << 14;               \
                uint32_t st_ = smb + AOFF_ST + (s2) * ASTG;                 \
                if (rank == 0) {                                            \
                    BULK_CP_MC(st_,         (const char*)g_akh + kb, 16384, mb, 3); \
                    BULK_CP_MC(st_ + 16384, (const char*)g_akl + kb, 16384, mb, 3); \
                } else {                                                    \
                    BULK_CP_MC(st_ + 32768, (const char*)g_avh + kb, 16384, mb, 3); \
                    BULK_CP_MC(st_ + 49152, (const char*)g_avl + kb, 16384, mb, 3); \
                }                                                           \
            } while (0)

            {
                size_t qb = ((size_t)(bh * 16 + rt)) << 15;
                MBARRIER_EXPECT_TX(smb + 64, 131072);
                BULK_CP(smb + AOFF_Q,         (const char*)g_aqh + qb, 32768, smb + 64);
                BULK_CP(smb + AOFF_Q + 32768, (const char*)g_aql + qb, 32768, smb + 64);
                LOADKV(0, 0, smb + 64);
                MBARRIER_EXPECT_TX(smb + 80, 65536);
                LOADKV(1, 1, smb + 80);
            }
            const uint64_t dQh = MAKE_SMEM_DESC(smb + AOFF_Q);
            const uint64_t dQl = MAKE_SMEM_DESC(smb + AOFF_Q + 32768);

            for (int i = 0; i < 32; ++i) {
                int s = i & 1, ph = (i >> 1) & 1;
                MBARRIER_WAIT_PARITY(smb + 64 + 16 * s, ph);
                if (i >= 2) MBARRIER_WAIT_PARITY(smb + 128 + 16 * s, ((i - 2) >> 1) & 1);
                uint32_t sreg = tmem + s * 64;
                uint32_t stg = smb + AOFF_ST + s * ASTG;
                uint64_t dKh = MAKE_SMEM_DESC(stg);
                uint64_t dKl = MAKE_SMEM_DESC(stg + 16384);
#pragma unroll
                for (int ch = 0; ch < 2; ++ch)
#pragma unroll
                for (int ks = 0; ks < 4; ++ks) {
                    uint64_t ao = ch * 1024 + ks * 2;
                    uint64_t bo = ch * 512 + ks * 2;
                    mma_f16_ss(sreg, dQh + ao, dKh + bo, IDESC_S, (ch | ks) != 0);
                    mma_f16_ss(sreg, dQl + ao, dKh + bo, IDESC_S, 1);
                    mma_f16_ss(sreg, dQh + ao, dKl + bo, IDESC_S, 1);
                }
                TCGEN05_COMMIT(smb + 96 + 16 * s);

                if (i >= 1) {
                    int j = i - 1, sj = j & 1, pj = (j >> 1) & 1;
                    MBARRIER_WAIT_PARITY(smb + 160 + 16 * sj, pj);
                    TCGEN05_FENCE_AFTER();
                    uint32_t stj = smb + AOFF_ST + sj * ASTG;
                    uint64_t dVh = MAKE_SMEM_DESC(stj + 32768);
                    uint64_t dVl = MAKE_SMEM_DESC(stj + 49152);
#pragma unroll
                    for (int ks = 0; ks < 4; ++ks) {
                        uint32_t ah = tmem + 256 + sj * 64 + ks * 8;
                        uint32_t al = tmem + 288 + sj * 64 + ks * 8;
                        uint64_t bo = (uint64_t)(ks * 2);
                        mma_f16_ts(tmem + 128, ah, dVh + bo, IDESC_PV, (j | ks) != 0);
                        mma_f16_ts(tmem + 128, al, dVh + bo, IDESC_PV, 1);
                        mma_f16_ts(tmem + 128, ah, dVl + bo, IDESC_PV, 1);
                    }
                    TCGEN05_COMMIT(smb + 192 + 16 * sj);
                    MBARRIER_WAIT_PARITY(smb + 192 + 16 * sj, pj);
                    if (i < 31) {
                        // stage sj now free on this CTA; sync with peer before
                        // multicasting the next chunk into it
                        MBARRIER_ARRIVE_CLUSTER(smb + 224 + 16 * sj, 0);
                        MBARRIER_ARRIVE_CLUSTER(smb + 224 + 16 * sj, 1);
                        MBARRIER_WAIT_PARITY(smb + 224 + 16 * sj, pj);
                        uint32_t fb = smb + 64 + 16 * ((i + 1) & 1);
                        MBARRIER_EXPECT_TX(fb, 65536);
                        LOADKV(i + 1, (i + 1) & 1, fb);
                    }
                }
            }
            {   // final PV: j = 31
                int sj = 1, pj = 1;
                MBARRIER_WAIT_PARITY(smb + 160 + 16 * sj, pj);
                TCGEN05_FENCE_AFTER();
                uint32_t stj = smb + AOFF_ST + sj * ASTG;
                uint64_t dVh = MAKE_SMEM_DESC(stj + 32768);
                uint64_t dVl = MAKE_SMEM_DESC(stj + 49152);
#pragma unroll
                for (int ks = 0; ks < 4; ++ks) {
                    uint32_t ah = tmem + 256 + sj * 64 + ks * 8;
                    uint32_t al = tmem + 288 + sj * 64 + ks * 8;
                    uint64_t bo = (uint64_t)(ks * 2);
                    mma_f16_ts(tmem + 128, ah, dVh + bo, IDESC_PV, 1);
                    mma_f16_ts(tmem + 128, al, dVh + bo, IDESC_PV, 1);
                    mma_f16_ts(tmem + 128, ah, dVl + bo, IDESC_PV, 1);
                }
                TCGEN05_COMMIT(smb + 192 + 16 * sj);
                MBARRIER_WAIT_PARITY(smb + 192 + 16 * sj, pj);
            }
#undef LOADKV
        }
    }

    float l = 0.0f;
    if (wid < 4) {
        const float* md_base = (const float*)(sm + AOFF_MADD);
        for (int i = 0; i < 32; ++i) {
            int s = i & 1, ph = (i >> 1) & 1;
            MBARRIER_WAIT_PARITY(smb + 96 + 16 * s, ph);
            TCGEN05_FENCE_AFTER();
            uint32_t r0[32], r1[32];
            TCGEN05_LD_32X32B_X32(r0, tmem + s * 64);
            TCGEN05_LD_32X32B_X32(r1, tmem + s * 64 + 32);
            TCGEN05_WAIT_LD();
            if (elect_one_pred()) MBARRIER_ARRIVE(smb + 128 + 16 * s);

            const float* md = md_base + i * 64;
#pragma unroll
            for (int j = 0; j < 32; ++j) {
                float e = __expf(__uint_as_float(r0[j]) + md[j]);
                l += e;
                r0[j] = __float_as_uint(e);
            }
#pragma unroll
            for (int j = 0; j < 32; ++j) {
                float e = __expf(__uint_as_float(r1[j]) + md[32 + j]);
                l += e;
                r1[j] = __float_as_uint(e);
            }
            uint32_t phv[32], plv[32];
#pragma unroll
            for (int p = 0; p < 16; ++p) {
                __nv_bfloat16 h0, h1, l0, l1;
                split_bf16(__uint_as_float(r0[2 * p]), h0, l0);
                split_bf16(__uint_as_float(r0[2 * p + 1]), h1, l1);
                __nv_bfloat162 hp(h0, h1), lp(l0, l1);
                phv[p] = *(uint32_t*)&hp;
                plv[p] = *(uint32_t*)&lp;
            }
#pragma unroll
            for (int p = 0; p < 16; ++p) {
                __nv_bfloat16 h0, h1, l0, l1;
                split_bf16(__uint_as_float(r1[2 * p]), h0, l0);
                split_bf16(__uint_as_float(r1[2 * p + 1]), h1, l1);
                __nv_bfloat162 hp(h0, h1), lp(l0, l1);
                phv[16 + p] = *(uint32_t*)&hp;
                plv[16 + p] = *(uint32_t*)&lp;
            }
            uint32_t wo = (uint32_t)wid << 21;
            TCGEN05_ST_32X32B_X32(tmem + 256 + s * 64 + wo, phv);
            TCGEN05_ST_32X32B_X32(tmem + 288 + s * 64 + wo, plv);
            TCGEN05_WAIT_ST();
            TCGEN05_FENCE_BEFORE();
            if (elect_one_pred()) MBARRIER_ARRIVE(smb + 160 + 16 * s);
        }
    }

    __syncthreads();

    if (wid < 4) {
        TCGEN05_FENCE_AFTER();
        float inv = 1.0f / l;
        int qrow = rt * 128 + wid * 32 + lid;
        int tok = b * 2048 + qrow;
        int rtt = tok >> 7, rr = tok & 127;
        int hh = bh & 15;
        __align__(16) __nv_bfloat16 hv[8], lv[8];
#pragma unroll
        for (int cb = 0; cb < 4; ++cb) {
            uint32_t r[32];
            TCGEN05_LD_32X32B_X32(r, tmem + 128 + cb * 32);
            TCGEN05_WAIT_LD();
            int c_ = hh * 2 + (cb >> 1);
            size_t tb = ((size_t)(c_ * NRT_A + rtt)) << 14;
            int kcb = (cb & 1) * 32;
#pragma unroll
            for (int j0 = 0; j0 < 32; j0 += 8) {
#pragma unroll
                for (int j = 0; j < 8; ++j)
                    split_bf16(__uint_as_float(r[j0 + j]) * inv, hv[j], lv[j]);
                uint32_t so = SMEM_SWIZZLE_128B((uint32_t)(rr * 128 + (kcb + j0) * 2));
                *(uint4*)((char*)g_chh + tb + so) = *(uint4*)hv;
                *(uint4*)((char*)g_cll + tb + so) = *(uint4*)lv;
            }
        }
        TCGEN05_FENCE_BEFORE();
    }

    __syncthreads();
    CLUSTER_SYNC();
    if (tid == 0) {
#pragma unroll
        for (int s = 0; s < 2; ++s) {
            MBARRIER_INVAL(smb + 64 + 16 * s);
            MBARRIER_INVAL(smb + 96 + 16 * s);
            MBARRIER_INVAL(smb + 128 + 16 * s);
            MBARRIER_INVAL(smb + 160 + 16 * s);
            MBARRIER_INVAL(smb + 192 + 16 * s);
            MBARRIER_INVAL(smb + 224 + 16 * s);
        }
    }
    __syncthreads();
    if (wid == 0) {
        TCGEN05_RELINQUISH();
        TCGEN05_DEALLOC(tmem, 512);
    }
    CLUSTER_SYNC();
#endif  // HAS_TCGEN05
}

// ============================================================
extern "C" void kernel_launch(void* const* d_in, const int* in_sizes, int n_in,
                              void* d_out, int out_size)
{
    const float* x    = (const float*)d_in[0];
    const float* mask = (const float*)d_in[1];
    const float* Wq   = (const float*)d_in[2];
    const float* bq   = (const float*)d_in[3];
    const float* Wk   = (const float*)d_in[4];
    const float* bk   = (const float*)d_in[5];
    const float* Wv   = (const float*)d_in[6];
    const float* bv   = (const float*)d_in[7];
    const float* Wo   = (const float*)d_in[8];
    const float* bo   = (const float*)d_in[9];
    float* out = (float*)d_out;

    __nv_bfloat16 *xh, *xl, *wh, *wl;
    cudaGetSymbolAddress((void**)&xh, g_xh);
    cudaGetSymbolAddress((void**)&xl, g_xl);
    cudaGetSymbolAddress((void**)&wh, g_wh);
    cudaGetSymbolAddress((void**)&wl, g_wl);

    const int WN = D_MODEL * D_MODEL;
    const int XN = M_TOK * D_MODEL;

    split_pack<<<XN / 8 / 256, 256>>>(x, xh, xl, NRT_A, XN / 8);
    split_pack<<<WN / 8 / 256, 256>>>(Wq, wh + 0ll * WN, wl + 0ll * WN, NRT_W, WN / 8);
    split_pack<<<WN / 8 / 256, 256>>>(Wk, wh + 1ll * WN, wl + 1ll * WN, NRT_W, WN / 8);
    split_pack<<<WN / 8 / 256, 256>>>(Wv, wh + 2ll * WN, wl + 2ll * WN, NRT_W, WN / 8);
    split_pack<<<WN / 8 / 256, 256>>>(Wo, wh + 3ll * WN, wl + 3ll * WN, NRT_W, WN / 8);

    cudaFuncSetAttribute(gemm_fused, cudaFuncAttributeMaxDynamicSharedMemorySize, GEMM_SMEM);
    cudaFuncSetAttribute(attn_tc, cudaFuncAttributeMaxDynamicSharedMemorySize, ATTN_SMEM);

    // fused QKV projections with packed-operand epilogues
    gemm_fused<<<dim3(8, 32, 3), 256, GEMM_SMEM>>>(0, bq, bk, bv, bo, out);

    // attention (writes packed ctx for O projection)
    attn_tc<<<dim3(16, 32), 160, ATTN_SMEM>>>(mask);

    // O projection -> final output
    gemm_fused<<<dim3(8, 32, 1), 256, GEMM_SMEM>>>(3, bq, bk, bv, bo, out);
}

// round 7
// speedup vs baseline: 1.2263x; 1.2263x over previous
#include <cuda_runtime.h>
#include <cuda_bf16.h>
#include <cstdint>

#define D_MODEL 2048
#define SEQ     2048
#define BATCH   2
#define NHEADS  16
#define HDIM    128
#define M_TOK   (BATCH*SEQ)   // 4096

#if defined(__CUDA_ARCH_FEAT_SM103_ALL) || defined(__CUDA_ARCH_FEAT_SM100_ALL) || \
    (defined(__CUDA_ARCH_SPECIFIC__) && (__CUDA_ARCH_SPECIFIC__ >= 1000))
#define HAS_TCGEN05 1
#else
#define HAS_TCGEN05 0
#endif

// ---- persistent scratch ----
__device__ float g_q[M_TOK * D_MODEL];
__device__ float g_k[M_TOK * D_MODEL];
__device__ float g_v[M_TOK * D_MODEL];
__device__ float g_ctx[M_TOK * D_MODEL];

__device__ __nv_bfloat16 g_xh[M_TOK * D_MODEL];
__device__ __nv_bfloat16 g_xl[M_TOK * D_MODEL];
__device__ __nv_bfloat16 g_chh[M_TOK * D_MODEL];
__device__ __nv_bfloat16 g_cll[M_TOK * D_MODEL];
__device__ __nv_bfloat16 g_wh[4][D_MODEL * D_MODEL];
__device__ __nv_bfloat16 g_wl[4][D_MODEL * D_MODEL];

__device__ __nv_bfloat16 g_aqh[M_TOK * D_MODEL];   // Q tiles: [bh][rt16][2ch x 16KB]
__device__ __nv_bfloat16 g_aql[M_TOK * D_MODEL];
__device__ __nv_bfloat16 g_akh[M_TOK * D_MODEL];   // K tiles: [bh][kt32][2ch x 8KB]
__device__ __nv_bfloat16 g_akl[M_TOK * D_MODEL];
__device__ __nv_bfloat16 g_avh[M_TOK * D_MODEL];   // V^T tiles: [bh][kt32][16KB]
__device__ __nv_bfloat16 g_avl[M_TOK * D_MODEL];

// ============================================================
// PTX helpers
// ============================================================
__device__ __forceinline__ uint32_t smem_u32(const void* p) {
    uint32_t a;
    asm("{ .reg .u64 t; cvta.to.shared.u64 t, %1; cvt.u32.u64 %0, t; }" : "=r"(a) : "l"(p));
    return a;
}
__device__ __forceinline__ uint32_t elect_one_pred() {
    uint32_t p;
    asm volatile("{ .reg .pred p; elect.sync _|p, 0xFFFFFFFF; selp.b32 %0, 1, 0, p; }" : "=r"(p));
    return p;
}
static constexpr uint64_t SMEM_DESC_BASE_SW128 =
    (uint64_t(2) << 61) | (uint64_t(1) << 46) | (uint64_t(64) << 32) | (uint64_t(1) << 16);
#define MAKE_SMEM_DESC(base_addr) \
    (SMEM_DESC_BASE_SW128 | ((uint64_t)((base_addr) >> 4) & 0x3FFF))
#define SMEM_SWIZZLE_128B(off) ((off) ^ (((off) >> 3) & 0x70))

#define MBARRIER_INIT(mbar, count) \
    asm volatile("mbarrier.init.shared.b64 [%0], %1;" \
                 :: "r"((uint32_t)(mbar)), "r"((uint32_t)(count)) : "memory")
#define MBARRIER_INVAL(mbar) \
    asm volatile("mbarrier.inval.shared.b64 [%0];" :: "r"((uint32_t)(mbar)) : "memory")
#define MBARRIER_EXPECT_TX(mbar, bytes) \
    asm volatile("mbarrier.arrive.expect_tx.shared.b64 _, [%0], %1;" \
                 :: "r"((uint32_t)(mbar)), "r"((uint32_t)(bytes)) : "memory")
#define MBARRIER_ARRIVE(mbar) \
    asm volatile("mbarrier.arrive.shared.b64 _, [%0];" :: "r"((uint32_t)(mbar)) : "memory")
#define MBARRIER_WAIT_PARITY(mbar, parity) do {                                          \
    uint32_t _m = (uint32_t)(mbar);                                                      \
    uint32_t _p = (uint32_t)(parity);                                                    \
    uint32_t _done;                                                                      \
    asm volatile("{ .reg .pred p; mbarrier.try_wait.parity.acquire.cta.shared::cta.b64 " \
                 "p, [%1], %2; selp.b32 %0, 1, 0, p; }"                                  \
                 : "=r"(_done) : "r"(_m), "r"(_p) : "memory");                           \
    if (!_done) {                                                                        \
        asm volatile("{ .reg .pred P1; WL_%=: "                                          \
                     "mbarrier.try_wait.parity.acquire.cta.shared::cta.b64 P1, [%0], %1, 0x989680; " \
                     "@P1 bra.uni WD_%=; bra.uni WL_%=; WD_%=: }"                        \
                     :: "r"(_m), "r"(_p) : "memory");                                    \
    }                                                                                    \
} while (0)

#define BULK_CP(dst_smem, src_gmem, bytes, mbar) \
    asm volatile("cp.async.bulk.shared::cluster.global.mbarrier::complete_tx::bytes " \
                 "[%0], [%1], %2, [%3];" \
                 :: "r"((uint32_t)(dst_smem)), "l"(src_gmem), "r"((uint32_t)(bytes)), \
                    "r"((uint32_t)(mbar)) : "memory")

#if HAS_TCGEN05
#define TCGEN05_ALLOC(smem_addr, nCols) \
    asm volatile("tcgen05.alloc.cta_group::1.sync.aligned.shared::cta.b32 [%0], %1;" \
                 :: "r"((uint32_t)(smem_addr)), "r"((uint32_t)(nCols)) : "memory")
#define TCGEN05_DEALLOC(tmem_addr, nCols) \
    asm volatile("tcgen05.dealloc.cta_group::1.sync.aligned.b32 %0, %1;" \
                 :: "r"(tmem_addr), "r"((uint32_t)(nCols)))
#define TCGEN05_RELINQUISH() \
    asm volatile("tcgen05.relinquish_alloc_permit.cta_group::1.sync.aligned;")
#define TCGEN05_COMMIT(mbar) \
    asm volatile("tcgen05.commit.cta_group::1.mbarrier::arrive::one.shared::cluster.b64 [%0];" \
                 :: "r"((uint32_t)(mbar)) : "memory")
#define TCGEN05_FENCE_AFTER() \
    asm volatile("tcgen05.fence::after_thread_sync;" ::: "memory")
#define TCGEN05_FENCE_BEFORE() \
    asm volatile("tcgen05.fence::before_thread_sync;" ::: "memory")
#define TCGEN05_WAIT_LD() \
    asm volatile("tcgen05.wait::ld.sync.aligned;" ::: "memory")
#define TCGEN05_WAIT_ST() \
    asm volatile("tcgen05.wait::st.sync.aligned;" ::: "memory")

#define TCGEN05_LD_32X32B_X32(r, tmem_addr) \
    asm volatile( \
        "tcgen05.ld.sync.aligned.32x32b.x32.b32 " \
        "{%0, %1, %2, %3, %4, %5, %6, %7, " \
        " %8, %9, %10, %11, %12, %13, %14, %15, " \
        " %16, %17, %18, %19, %20, %21, %22, %23, " \
        " %24, %25, %26, %27, %28, %29, %30, %31}, [%32];" \
        : "=r"((r)[0]),  "=r"((r)[1]),  "=r"((r)[2]),  "=r"((r)[3]), \
          "=r"((r)[4]),  "=r"((r)[5]),  "=r"((r)[6]),  "=r"((r)[7]), \
          "=r"((r)[8]),  "=r"((r)[9]),  "=r"((r)[10]), "=r"((r)[11]), \
          "=r"((r)[12]), "=r"((r)[13]), "=r"((r)[14]), "=r"((r)[15]), \
          "=r"((r)[16]), "=r"((r)[17]), "=r"((r)[18]), "=r"((r)[19]), \
          "=r"((r)[20]), "=r"((r)[21]), "=r"((r)[22]), "=r"((r)[23]), \
          "=r"((r)[24]), "=r"((r)[25]), "=r"((r)[26]), "=r"((r)[27]), \
          "=r"((r)[28]), "=r"((r)[29]), "=r"((r)[30]), "=r"((r)[31]) \
        : "r"(tmem_addr))

#define TCGEN05_ST_32X32B_X32(tmem_addr, r) \
    asm volatile( \
        "tcgen05.st.sync.aligned.32x32b.x32.b32 [%0], " \
        "{%1, %2, %3, %4, %5, %6, %7, %8, " \
        " %9, %10, %11, %12, %13, %14, %15, %16, " \
        " %17, %18, %19, %20, %21, %22, %23, %24, " \
        " %25, %26, %27, %28, %29, %30, %31, %32};" \
        :: "r"(tmem_addr), \
           "r"((r)[0]),  "r"((r)[1]),  "r"((r)[2]),  "r"((r)[3]), \
           "r"((r)[4]),  "r"((r)[5]),  "r"((r)[6]),  "r"((r)[7]), \
           "r"((r)[8]),  "r"((r)[9]),  "r"((r)[10]), "r"((r)[11]), \
           "r"((r)[12]), "r"((r)[13]), "r"((r)[14]), "r"((r)[15]), \
           "r"((r)[16]), "r"((r)[17]), "r"((r)[18]), "r"((r)[19]), \
           "r"((r)[20]), "r"((r)[21]), "r"((r)[22]), "r"((r)[23]), \
           "r"((r)[24]), "r"((r)[25]), "r"((r)[26]), "r"((r)[27]), \
           "r"((r)[28]), "r"((r)[29]), "r"((r)[30]), "r"((r)[31]) \
        : "memory")

__device__ __forceinline__ void mma_f16_ss(uint32_t d_tmem, uint64_t a_desc, uint64_t b_desc,
                                           uint32_t idesc, uint32_t enable) {
    asm volatile(
        "{\n\t"
        ".reg .pred p;\n\t"
        "setp.ne.u32 p, %4, 0;\n\t"
        "tcgen05.mma.cta_group::1.kind::f16 [%0], %1, %2, %3, {%5, %5, %5, %5}, p;\n\t"
        "}"
        :: "r"(d_tmem), "l"(a_desc), "l"(b_desc), "r"(idesc), "r"(enable), "r"(0u)
        : "memory");
}
__device__ __forceinline__ void mma_f16_ts(uint32_t d_tmem, uint32_t a_tmem, uint64_t b_desc,
                                           uint32_t idesc, uint32_t enable) {
    asm volatile(
        "{\n\t"
        ".reg .pred p;\n\t"
        "setp.ne.u32 p, %4, 0;\n\t"
        "tcgen05.mma.cta_group::1.kind::f16 [%0], [%1], %2, %3, {%5, %5, %5, %5}, p;\n\t"
        "}"
        :: "r"(d_tmem), "r"(a_tmem), "l"(b_desc), "r"(idesc), "r"(enable), "r"(0u)
        : "memory");
}
#endif  // HAS_TCGEN05

__device__ __forceinline__ void split_bf16(float f, __nv_bfloat16& h, __nv_bfloat16& l) {
    h = __float2bfloat16(f);
    l = __float2bfloat16(f - __bfloat162float(h));
}

// ============================================================
// Merged split+pack: x (seg 0) and W0..W3 (segs 1..4) in ONE launch.
// ============================================================
#define XN8 (M_TOK * D_MODEL / 8)        // 1048576
#define WN8 (D_MODEL * D_MODEL / 8)      // 524288

__global__ __launch_bounds__(256) void split_all(
    const float* __restrict__ x, const float* __restrict__ W0,
    const float* __restrict__ W1, const float* __restrict__ W2,
    const float* __restrict__ W3)
{
    int i = blockIdx.x * blockDim.x + threadIdx.x;
    const float* src;
    __nv_bfloat16 *hi, *lo;
    int nrt, li;
    if (i < XN8) {
        src = x; hi = g_xh; lo = g_xl; nrt = 32; li = i;
    } else {
        int w = (i - XN8) >> 19;          // / WN8 (2^19)
        li = (i - XN8) & (WN8 - 1);
        src = (w == 0) ? W0 : (w == 1) ? W1 : (w == 2) ? W2 : W3;
        hi = g_wh[w]; lo = g_wl[w]; nrt = 16;
    }
    int elem = li * 8;
    int row = elem >> 11;
    int col = elem & 2047;
    int rt = row >> 7, r = row & 127;
    int c  = col >> 6, kc = col & 63;
    size_t tb = ((size_t)(c * nrt + rt)) << 14;
    uint32_t so = SMEM_SWIZZLE_128B((uint32_t)(r * 128 + kc * 2));

    float4 v0 = ((const float4*)src)[(size_t)li * 2];
    float4 v1 = ((const float4*)src)[(size_t)li * 2 + 1];
    float f[8] = {v0.x, v0.y, v0.z, v0.w, v1.x, v1.y, v1.z, v1.w};
    __align__(16) __nv_bfloat16 h[8], l[8];
#pragma unroll
    for (int j = 0; j < 8; j++) split_bf16(f[j], h[j], l[j]);
    *(uint4*)((char*)hi + tb + so) = *(uint4*)h;
    *(uint4*)((char*)lo + tb + so) = *(uint4*)l;
}

// split+pack for ctx only (after attention)
__global__ __launch_bounds__(256) void split_ctx()
{
    int i = blockIdx.x * blockDim.x + threadIdx.x;
    int elem = i * 8;
    int row = elem >> 11;
    int col = elem & 2047;
    int rt = row >> 7, r = row & 127;
    int c  = col >> 6, kc = col & 63;
    size_t tb = ((size_t)(c * 32 + rt)) << 14;
    uint32_t so = SMEM_SWIZZLE_128B((uint32_t)(r * 128 + kc * 2));

    float4 v0 = ((const float4*)g_ctx)[(size_t)i * 2];
    float4 v1 = ((const float4*)g_ctx)[(size_t)i * 2 + 1];
    float f[8] = {v0.x, v0.y, v0.z, v0.w, v1.x, v1.y, v1.z, v1.w};
    __align__(16) __nv_bfloat16 h[8], l[8];
#pragma unroll
    for (int j = 0; j < 8; j++) split_bf16(f[j], h[j], l[j]);
    *(uint4*)((char*)g_chh + tb + so) = *(uint4*)h;
    *(uint4*)((char*)g_cll + tb + so) = *(uint4*)l;
}

// ============================================================
// Merged attention operand packer: blockIdx.y = 0(Q) / 1(K) / 2(V^T)
// ============================================================
__global__ __launch_bounds__(256) void pack_attn()
{
    int i = blockIdx.x * blockDim.x + threadIdx.x;
    int which = blockIdx.y;
    int elem = i * 8;
    int tok = elem >> 11, col = elem & 2047;
    int b = tok >> 11, s = tok & 2047;
    int h = col >> 7, d = col & 127;
    int bh = b * 16 + h;

    if (which == 0) {
        int rt = s >> 7, r = s & 127, ch = d >> 6, kc = d & 63;
        size_t tb = ((size_t)(((bh * 16 + rt) * 2) + ch)) << 14;
        uint32_t so = SMEM_SWIZZLE_128B((uint32_t)(r * 128 + kc * 2));
        const float* src = g_q + (size_t)tok * 2048 + col;
        float4 v0 = *(const float4*)src, v1 = *(const float4*)(src + 4);
        float f[8] = {v0.x, v0.y, v0.z, v0.w, v1.x, v1.y, v1.z, v1.w};
        __align__(16) __nv_bfloat16 hh[8], ll[8];
#pragma unroll
        for (int j = 0; j < 8; j++) split_bf16(f[j], hh[j], ll[j]);
        *(uint4*)((char*)g_aqh + tb + so) = *(uint4*)hh;
        *(uint4*)((char*)g_aql + tb + so) = *(uint4*)ll;
    } else if (which == 1) {
        int kt = s >> 6, r = s & 63, ch = d >> 6, kc = d & 63;
        size_t tb = ((size_t)(((bh * 32 + kt) * 2) + ch)) << 13;
        uint32_t so = SMEM_SWIZZLE_128B((uint32_t)(r * 128 + kc * 2));
        const float* src = g_k + (size_t)tok * 2048 + col;
        float4 v0 = *(const float4*)src, v1 = *(const float4*)(src + 4);
        float f[8] = {v0.x, v0.y, v0.z, v0.w, v1.x, v1.y, v1.z, v1.w};
        __align__(16) __nv_bfloat16 hh[8], ll[8];
#pragma unroll
        for (int j = 0; j < 8; j++) split_bf16(f[j], hh[j], ll[j]);
        *(uint4*)((char*)g_akh + tb + so) = *(uint4*)hh;
        *(uint4*)((char*)g_akl + tb + so) = *(uint4*)ll;
    } else {
        int kt = s >> 6, sc = s & 63;
        size_t tb = ((size_t)(bh * 32 + kt)) << 14;
        const float* src = g_v + (size_t)tok * 2048 + col;
        float4 v0 = *(const float4*)src, v1 = *(const float4*)(src + 4);
        float f[8] = {v0.x, v0.y, v0.z, v0.w, v1.x, v1.y, v1.z, v1.w};
#pragma unroll
        for (int j = 0; j < 8; j++) {
            __nv_bfloat16 hh, ll;
            split_bf16(f[j], hh, ll);
            uint32_t off = SMEM_SWIZZLE_128B((uint32_t)((d + j) * 128 + sc * 2));
            *(__nv_bfloat16*)((char*)g_avh + tb + off) = hh;
            *(__nv_bfloat16*)((char*)g_avl + tb + off) = ll;
        }
    }
}

// ============================================================
// tcgen05 GEMM (NT), no clusters. mode = blockIdx.z + mode_base:
//   0/1/2 = Q/K/V projection (A = x), 3 = O projection (A = ctx)
// Tile 128(M) x 256(N), K-chunk 64 bf16, 3-MMA hi/lo split.
// ============================================================
#define NCH  32
#define NRT_A 32
#define NRT_W 16
#define TIL  16384
#define STG  (6 * TIL)
#define SMB0 1024
#define GEMM_SMEM (SMB0 + 2 * STG)
#define GEMM_IDESC 0x8400490u

__global__ __launch_bounds__(256) void gemm_tc(
    int mode_base, const float* __restrict__ b0, const float* __restrict__ b1,
    const float* __restrict__ b2, const float* __restrict__ b3,
    float* __restrict__ out)
{
#if HAS_TCGEN05
    extern __shared__ char sm[];
    const uint32_t smb = smem_u32(sm);
    const int tid = threadIdx.x;
    const int wid = tid >> 5;
    const int lid = tid & 31;
    const int rm = blockIdx.y;
    const int bx = blockIdx.x;
    const int mode = mode_base + blockIdx.z;

    const __nv_bfloat16* Ah = (mode < 3) ? g_xh : g_chh;
    const __nv_bfloat16* Al = (mode < 3) ? g_xl : g_cll;
    const __nv_bfloat16* Bh = g_wh[mode];
    const __nv_bfloat16* Bl = g_wl[mode];
    const float* bias = (mode == 0) ? b0 : (mode == 1) ? b1 : (mode == 2) ? b2 : b3;
    const float alpha = (mode == 0) ? 0.08838834764831845f : 1.0f;
    float* C = (mode == 0) ? g_q : (mode == 1) ? g_k : (mode == 2) ? g_v : out;

    if (wid == 0) TCGEN05_ALLOC(smb + 0, 256);
    if (tid == 0) {
#pragma unroll
        for (int s = 0; s < 2; ++s) {
            MBARRIER_INIT(smb + 64 + 16 * s, 1);
            MBARRIER_INIT(smb + 96 + 16 * s, 1);
        }
    }
    __syncthreads();

    uint32_t tmem;
    asm volatile("ld.shared.b32 %0, [%1];" : "=r"(tmem) : "r"(smb + 0));

    if (wid == 0 && elect_one_pred()) {
#define LOAD_CHUNK(c, s)                                                        \
        do {                                                                    \
            uint32_t st = smb + SMB0 + (s) * STG;                               \
            uint32_t fb = smb + 64 + 16 * (s);                                  \
            size_t ao = ((size_t)((c) * NRT_A + rm)) << 14;                     \
            size_t bo = ((size_t)((c) * NRT_W + 2 * bx)) << 14;                 \
            MBARRIER_EXPECT_TX(fb, 6 * TIL);                                    \
            BULK_CP(st,           (const char*)Ah + ao, TIL,     fb);           \
            BULK_CP(st + TIL,     (const char*)Al + ao, TIL,     fb);           \
            BULK_CP(st + 2 * TIL, (const char*)Bh + bo, 2 * TIL, fb);           \
            BULK_CP(st + 4 * TIL, (const char*)Bl + bo, 2 * TIL, fb);           \
        } while (0)

        LOAD_CHUNK(0, 0);
        LOAD_CHUNK(1, 1);

        for (int c = 0; c < NCH; ++c) {
            int s = c & 1, ph = (c >> 1) & 1;
            uint32_t st = smb + SMB0 + s * STG;
            MBARRIER_WAIT_PARITY(smb + 64 + 16 * s, ph);
            uint64_t dAh = MAKE_SMEM_DESC(st);
            uint64_t dAl = MAKE_SMEM_DESC(st + TIL);
            uint64_t dBh = MAKE_SMEM_DESC(st + 2 * TIL);
            uint64_t dBl = MAKE_SMEM_DESC(st + 4 * TIL);
#pragma unroll
            for (int ks = 0; ks < 4; ++ks) {
                mma_f16_ss(tmem, dAh + ks * 2, dBh + ks * 2, GEMM_IDESC, (c | ks) != 0);
                mma_f16_ss(tmem, dAl + ks * 2, dBh + ks * 2, GEMM_IDESC, 1);
                mma_f16_ss(tmem, dAh + ks * 2, dBl + ks * 2, GEMM_IDESC, 1);
            }
            TCGEN05_COMMIT(smb + 96 + 16 * s);
            if (c + 2 < NCH) {
                MBARRIER_WAIT_PARITY(smb + 96 + 16 * s, ph);
                LOAD_CHUNK(c + 2, s);
            }
        }
        MBARRIER_WAIT_PARITY(smb + 96 + 16 * ((NCH - 1) & 1), ((NCH - 1) >> 1) & 1);
#undef LOAD_CHUNK
    }
    __syncthreads();
    TCGEN05_FENCE_AFTER();

    const int wg = wid >> 2;
    const int sub = wid & 3;
    const int m = blockIdx.y * 128 + sub * 32 + lid;
    float* crow = C + (size_t)m * D_MODEL;
#pragma unroll
    for (int cb = 0; cb < 4; ++cb) {
        uint32_t r[32];
        TCGEN05_LD_32X32B_X32(r, tmem + wg * 128 + cb * 32);
        TCGEN05_WAIT_LD();
        int n0 = bx * 256 + wg * 128 + cb * 32;
#pragma unroll
        for (int j = 0; j < 32; j += 4) {
            float4 o;
            o.x = (__uint_as_float(r[j + 0]) + bias[n0 + j + 0]) * alpha;
            o.y = (__uint_as_float(r[j + 1]) + bias[n0 + j + 1]) * alpha;
            o.z = (__uint_as_float(r[j + 2]) + bias[n0 + j + 2]) * alpha;
            o.w = (__uint_as_float(r[j + 3]) + bias[n0 + j + 3]) * alpha;
            *(float4*)(crow + n0 + j) = o;
        }
    }
    TCGEN05_FENCE_BEFORE();

    __syncthreads();
    if (tid == 0) {
#pragma unroll
        for (int s = 0; s < 2; ++s) {
            MBARRIER_INVAL(smb + 64 + 16 * s);
            MBARRIER_INVAL(smb + 96 + 16 * s);
        }
    }
    __syncthreads();
    if (wid == 0) {
        TCGEN05_RELINQUISH();
        TCGEN05_DEALLOC(tmem, 256);
    }
#endif
}

// ============================================================
// tcgen05 flash attention (R5 version, no clusters)
// ============================================================
#define AOFF_Q    1024
#define AOFF_MADD 66560
#define AOFF_ST   74752
#define ASTG      65536
#define ATTN_SMEM 205824
#define IDESC_S   0x8100490u
#define IDESC_PV  0x8200490u

__global__ __launch_bounds__(160) void attn_tc(const float* __restrict__ mask)
{
#if HAS_TCGEN05
    extern __shared__ char sm[];
    const uint32_t smb = smem_u32(sm);
    const int tid = threadIdx.x;
    const int wid = tid >> 5;
    const int lid = tid & 31;
    const int rt = blockIdx.x;
    const int bh = blockIdx.y;
    const int b = bh >> 4;

    if (wid == 0) TCGEN05_ALLOC(smb + 0, 512);
    if (tid == 0) {
#pragma unroll
        for (int s = 0; s < 2; ++s) {
            MBARRIER_INIT(smb + 64 + 16 * s, 1);    // full_kv
            MBARRIER_INIT(smb + 96 + 16 * s, 1);    // s_full (commit)
            MBARRIER_INIT(smb + 128 + 16 * s, 4);   // smax_free
            MBARRIER_INIT(smb + 160 + 16 * s, 4);   // p_ready
            MBARRIER_INIT(smb + 192 + 16 * s, 1);   // pv_done (commit)
        }
    }
    for (int j = tid; j < SEQ; j += 160) {
        float mv = mask[b * SEQ + j];
        ((float*)(sm + AOFF_MADD))[j] = (1.0f - mv) * -1e30f;
    }
    __syncthreads();

    uint32_t tmem;
    asm volatile("ld.shared.b32 %0, [%1];" : "=r"(tmem) : "r"(smb + 0));

    if (wid == 4) {
        if (elect_one_pred()) {
#define LOADKV(i2, s2, mb)                                              \
            do {                                                        \
                size_t kb = ((size_t)(bh * 32 + (i2))) << 14;           \
                uint32_t st_ = smb + AOFF_ST + (s2) * ASTG;             \
                BULK_CP(st_,         (const char*)g_akh + kb, 16384, mb); \
                BULK_CP(st_ + 16384, (const char*)g_akl + kb, 16384, mb); \
                BULK_CP(st_ + 32768, (const char*)g_avh + kb, 16384, mb); \
                BULK_CP(st_ + 49152, (const char*)g_avl + kb, 16384, mb); \
            } while (0)

            {
                size_t qb = ((size_t)(bh * 16 + rt)) << 15;
                MBARRIER_EXPECT_TX(smb + 64, 131072);
                BULK_CP(smb + AOFF_Q,         (const char*)g_aqh + qb, 32768, smb + 64);
                BULK_CP(smb + AOFF_Q + 32768, (const char*)g_aql + qb, 32768, smb + 64);
                LOADKV(0, 0, smb + 64);
                MBARRIER_EXPECT_TX(smb + 80, 65536);
                LOADKV(1, 1, smb + 80);
            }
            const uint64_t dQh = MAKE_SMEM_DESC(smb + AOFF_Q);
            const uint64_t dQl = MAKE_SMEM_DESC(smb + AOFF_Q + 32768);

            for (int i = 0; i < 32; ++i) {
                int s = i & 1, ph = (i >> 1) & 1;
                MBARRIER_WAIT_PARITY(smb + 64 + 16 * s, ph);
                if (i >= 2) MBARRIER_WAIT_PARITY(smb + 128 + 16 * s, ((i - 2) >> 1) & 1);
                uint32_t sreg = tmem + s * 64;
                uint32_t stg = smb + AOFF_ST + s * ASTG;
                uint64_t dKh = MAKE_SMEM_DESC(stg);
                uint64_t dKl = MAKE_SMEM_DESC(stg + 16384);
#pragma unroll
                for (int ch = 0; ch < 2; ++ch)
#pragma unroll
                for (int ks = 0; ks < 4; ++ks) {
                    uint64_t ao = ch * 1024 + ks * 2;
                    uint64_t bo = ch * 512 + ks * 2;
                    mma_f16_ss(sreg, dQh + ao, dKh + bo, IDESC_S, (ch | ks) != 0);
                    mma_f16_ss(sreg, dQl + ao, dKh + bo, IDESC_S, 1);
                    mma_f16_ss(sreg, dQh + ao, dKl + bo, IDESC_S, 1);
                }
                TCGEN05_COMMIT(smb + 96 + 16 * s);

                if (i >= 1) {
                    int j = i - 1, sj = j & 1, pj = (j >> 1) & 1;
                    MBARRIER_WAIT_PARITY(smb + 160 + 16 * sj, pj);
                    TCGEN05_FENCE_AFTER();
                    uint32_t stj = smb + AOFF_ST + sj * ASTG;
                    uint64_t dVh = MAKE_SMEM_DESC(stj + 32768);
                    uint64_t dVl = MAKE_SMEM_DESC(stj + 49152);
#pragma unroll
                    for (int ks = 0; ks < 4; ++ks) {
                        uint32_t ah = tmem + 256 + sj * 64 + ks * 8;
                        uint32_t al = tmem + 288 + sj * 64 + ks * 8;
                        uint64_t bo = (uint64_t)(ks * 2);
                        mma_f16_ts(tmem + 128, ah, dVh + bo, IDESC_PV, (j | ks) != 0);
                        mma_f16_ts(tmem + 128, al, dVh + bo, IDESC_PV, 1);
                        mma_f16_ts(tmem + 128, ah, dVl + bo, IDESC_PV, 1);
                    }
                    TCGEN05_COMMIT(smb + 192 + 16 * sj);
                    MBARRIER_WAIT_PARITY(smb + 192 + 16 * sj, pj);
                    if (i < 31) {
                        uint32_t fb = smb + 64 + 16 * ((i + 1) & 1);
                        MBARRIER_EXPECT_TX(fb, 65536);
                        LOADKV(i + 1, (i + 1) & 1, fb);
                    }
                }
            }
            {   // final PV: j = 31
                int sj = 1, pj = 1;
                MBARRIER_WAIT_PARITY(smb + 160 + 16 * sj, pj);
                TCGEN05_FENCE_AFTER();
                uint32_t stj = smb + AOFF_ST + sj * ASTG;
                uint64_t dVh = MAKE_SMEM_DESC(stj + 32768);
                uint64_t dVl = MAKE_SMEM_DESC(stj + 49152);
#pragma unroll
                for (int ks = 0; ks < 4; ++ks) {
                    uint32_t ah = tmem + 256 + sj * 64 + ks * 8;
                    uint32_t al = tmem + 288 + sj * 64 + ks * 8;
                    uint64_t bo = (uint64_t)(ks * 2);
                    mma_f16_ts(tmem + 128, ah, dVh + bo, IDESC_PV, 1);
                    mma_f16_ts(tmem + 128, al, dVh + bo, IDESC_PV, 1);
                    mma_f16_ts(tmem + 128, ah, dVl + bo, IDESC_PV, 1);
                }
                TCGEN05_COMMIT(smb + 192 + 16 * sj);
                MBARRIER_WAIT_PARITY(smb + 192 + 16 * sj, pj);
            }
#undef LOADKV
        }
    }

    float l = 0.0f;
    if (wid < 4) {
        const float* md_base = (const float*)(sm + AOFF_MADD);
        for (int i = 0; i < 32; ++i) {
            int s = i & 1, ph = (i >> 1) & 1;
            MBARRIER_WAIT_PARITY(smb + 96 + 16 * s, ph);
            TCGEN05_FENCE_AFTER();
            uint32_t r0[32], r1[32];
            TCGEN05_LD_32X32B_X32(r0, tmem + s * 64);
            TCGEN05_LD_32X32B_X32(r1, tmem + s * 64 + 32);
            TCGEN05_WAIT_LD();
            if (elect_one_pred()) MBARRIER_ARRIVE(smb + 128 + 16 * s);

            const float* md = md_base + i * 64;
#pragma unroll
            for (int j = 0; j < 32; ++j) {
                float e = __expf(__uint_as_float(r0[j]) + md[j]);
                l += e;
                r0[j] = __float_as_uint(e);
            }
#pragma unroll
            for (int j = 0; j < 32; ++j) {
                float e = __expf(__uint_as_float(r1[j]) + md[32 + j]);
                l += e;
                r1[j] = __float_as_uint(e);
            }
            uint32_t phv[32], plv[32];
#pragma unroll
            for (int p = 0; p < 16; ++p) {
                __nv_bfloat16 h0, h1, l0, l1;
                split_bf16(__uint_as_float(r0[2 * p]), h0, l0);
                split_bf16(__uint_as_float(r0[2 * p + 1]), h1, l1);
                __nv_bfloat162 hp(h0, h1), lp(l0, l1);
                phv[p] = *(uint32_t*)&hp;
                plv[p] = *(uint32_t*)&lp;
            }
#pragma unroll
            for (int p = 0; p < 16; ++p) {
                __nv_bfloat16 h0, h1, l0, l1;
                split_bf16(__uint_as_float(r1[2 * p]), h0, l0);
                split_bf16(__uint_as_float(r1[2 * p + 1]), h1, l1);
                __nv_bfloat162 hp(h0, h1), lp(l0, l1);
                phv[16 + p] = *(uint32_t*)&hp;
                plv[16 + p] = *(uint32_t*)&lp;
            }
            uint32_t wo = (uint32_t)wid << 21;
            TCGEN05_ST_32X32B_X32(tmem + 256 + s * 64 + wo, phv);
            TCGEN05_ST_32X32B_X32(tmem + 288 + s * 64 + wo, plv);
            TCGEN05_WAIT_ST();
            TCGEN05_FENCE_BEFORE();
            if (elect_one_pred()) MBARRIER_ARRIVE(smb + 160 + 16 * s);
        }
    }

    __syncthreads();

    if (wid < 4) {
        TCGEN05_FENCE_AFTER();
        float inv = 1.0f / l;
        int qrow = rt * 128 + wid * 32 + lid;
        float* dst = g_ctx + ((size_t)(b * SEQ + qrow)) * D_MODEL + (bh & 15) * HDIM;
#pragma unroll
        for (int cb = 0; cb < 4; ++cb) {
            uint32_t r[32];
            TCGEN05_LD_32X32B_X32(r, tmem + 128 + cb * 32);
            TCGEN05_WAIT_LD();
#pragma unroll
            for (int j = 0; j < 32; j += 4) {
                float4 o;
                o.x = __uint_as_float(r[j + 0]) * inv;
                o.y = __uint_as_float(r[j + 1]) * inv;
                o.z = __uint_as_float(r[j + 2]) * inv;
                o.w = __uint_as_float(r[j + 3]) * inv;
                *(float4*)(dst + cb * 32 + j) = o;
            }
        }
        TCGEN05_FENCE_BEFORE();
    }

    __syncthreads();
    if (tid == 0) {
#pragma unroll
        for (int s = 0; s < 2; ++s) {
            MBARRIER_INVAL(smb + 64 + 16 * s);
            MBARRIER_INVAL(smb + 96 + 16 * s);
            MBARRIER_INVAL(smb + 128 + 16 * s);
            MBARRIER_INVAL(smb + 160 + 16 * s);
            MBARRIER_INVAL(smb + 192 + 16 * s);
        }
    }
    __syncthreads();
    if (wid == 0) {
        TCGEN05_RELINQUISH();
        TCGEN05_DEALLOC(tmem, 512);
    }
#endif  // HAS_TCGEN05
}

// ============================================================
extern "C" void kernel_launch(void* const* d_in, const int* in_sizes, int n_in,
                              void* d_out, int out_size)
{
    const float* x    = (const float*)d_in[0];
    const float* mask = (const float*)d_in[1];
    const float* Wq   = (const float*)d_in[2];
    const float* bq   = (const float*)d_in[3];
    const float* Wk   = (const float*)d_in[4];
    const float* bk   = (const float*)d_in[5];
    const float* Wv   = (const float*)d_in[6];
    const float* bv   = (const float*)d_in[7];
    const float* Wo   = (const float*)d_in[8];
    const float* bo   = (const float*)d_in[9];
    float* out = (float*)d_out;

    const int XN = M_TOK * D_MODEL;
    const int TOTAL8 = XN8 + 4 * WN8;   // 3145728

    cudaFuncSetAttribute(gemm_tc, cudaFuncAttributeMaxDynamicSharedMemorySize, GEMM_SMEM);
    cudaFuncSetAttribute(attn_tc, cudaFuncAttributeMaxDynamicSharedMemorySize, ATTN_SMEM);

    // 1. split + pack all GEMM operands (x + 4 weights) in one launch
    split_all<<<TOTAL8 / 256, 256>>>(x, Wq, Wk, Wv, Wo);

    // 2. QKV projections, one launch (grid z = mode)
    gemm_tc<<<dim3(8, 32, 3), 256, GEMM_SMEM>>>(0, bq, bk, bv, bo, out);

    // 3. pack attention operands (Q/K/V^T) in one launch
    pack_attn<<<dim3(XN / 8 / 256, 3), 256>>>();

    // 4. attention
    attn_tc<<<dim3(16, 32), 160, ATTN_SMEM>>>(mask);

    // 5. split + pack ctx
    split_ctx<<<XN / 8 / 256, 256>>>();

    // 6. O projection -> output
    gemm_tc<<<dim3(8, 32, 1), 256, GEMM_SMEM>>>(3, bq, bk, bv, bo, out);
}

// round 9
// speedup vs baseline: 1.4543x; 1.1859x over previous
#include <cuda_runtime.h>
#include <cuda_bf16.h>
#include <cstdint>

#define D_MODEL 2048
#define SEQ     2048
#define BATCH   2
#define NHEADS  16
#define HDIM    128
#define M_TOK   (BATCH*SEQ)   // 4096

#if defined(__CUDA_ARCH_FEAT_SM103_ALL) || defined(__CUDA_ARCH_FEAT_SM100_ALL) || \
    (defined(__CUDA_ARCH_SPECIFIC__) && (__CUDA_ARCH_SPECIFIC__ >= 1000))
#define HAS_TCGEN05 1
#else
#define HAS_TCGEN05 0
#endif

// ---- persistent scratch ----
__device__ float g_q[M_TOK * D_MODEL];
__device__ float g_k[M_TOK * D_MODEL];
__device__ float g_v[M_TOK * D_MODEL];
__device__ float g_ctx[M_TOK * D_MODEL];

__device__ __nv_bfloat16 g_xh[M_TOK * D_MODEL];
__device__ __nv_bfloat16 g_xl[M_TOK * D_MODEL];
__device__ __nv_bfloat16 g_chh[M_TOK * D_MODEL];
__device__ __nv_bfloat16 g_cll[M_TOK * D_MODEL];
__device__ __nv_bfloat16 g_wh[4][D_MODEL * D_MODEL];
__device__ __nv_bfloat16 g_wl[4][D_MODEL * D_MODEL];

__device__ __nv_bfloat16 g_aqh[M_TOK * D_MODEL];   // Q tiles: [bh][rt16][2ch x 16KB]
__device__ __nv_bfloat16 g_aql[M_TOK * D_MODEL];
__device__ __nv_bfloat16 g_akh[M_TOK * D_MODEL];   // K tiles: [bh][kt32][2ch x 8KB]
__device__ __nv_bfloat16 g_akl[M_TOK * D_MODEL];
__device__ __nv_bfloat16 g_avh[M_TOK * D_MODEL];   // V^T tiles: [bh][kt32][16KB]
__device__ __nv_bfloat16 g_avl[M_TOK * D_MODEL];

// ============================================================
// PTX helpers
// ============================================================
__device__ __forceinline__ uint32_t smem_u32(const void* p) {
    uint32_t a;
    asm("{ .reg .u64 t; cvta.to.shared.u64 t, %1; cvt.u32.u64 %0, t; }" : "=r"(a) : "l"(p));
    return a;
}
__device__ __forceinline__ uint32_t elect_one_pred() {
    uint32_t p;
    asm volatile("{ .reg .pred p; elect.sync _|p, 0xFFFFFFFF; selp.b32 %0, 1, 0, p; }" : "=r"(p));
    return p;
}
static constexpr uint64_t SMEM_DESC_BASE_SW128 =
    (uint64_t(2) << 61) | (uint64_t(1) << 46) | (uint64_t(64) << 32) | (uint64_t(1) << 16);
#define MAKE_SMEM_DESC(base_addr) \
    (SMEM_DESC_BASE_SW128 | ((uint64_t)((base_addr) >> 4) & 0x3FFF))
#define SMEM_SWIZZLE_128B(off) ((off) ^ (((off) >> 3) & 0x70))

#define MBARRIER_INIT(mbar, count) \
    asm volatile("mbarrier.init.shared.b64 [%0], %1;" \
                 :: "r"((uint32_t)(mbar)), "r"((uint32_t)(count)) : "memory")
#define MBARRIER_INVAL(mbar) \
    asm volatile("mbarrier.inval.shared.b64 [%0];" :: "r"((uint32_t)(mbar)) : "memory")
#define MBARRIER_EXPECT_TX(mbar, bytes) \
    asm volatile("mbarrier.arrive.expect_tx.shared.b64 _, [%0], %1;" \
                 :: "r"((uint32_t)(mbar)), "r"((uint32_t)(bytes)) : "memory")
#define MBARRIER_ARRIVE(mbar) \
    asm volatile("mbarrier.arrive.shared.b64 _, [%0];" :: "r"((uint32_t)(mbar)) : "memory")
#define MBARRIER_WAIT_PARITY(mbar, parity) do {                                          \
    uint32_t _m = (uint32_t)(mbar);                                                      \
    uint32_t _p = (uint32_t)(parity);                                                    \
    uint32_t _done;                                                                      \
    asm volatile("{ .reg .pred p; mbarrier.try_wait.parity.acquire.cta.shared::cta.b64 " \
                 "p, [%1], %2; selp.b32 %0, 1, 0, p; }"                                  \
                 : "=r"(_done) : "r"(_m), "r"(_p) : "memory");                           \
    if (!_done) {                                                                        \
        asm volatile("{ .reg .pred P1; WL_%=: "                                          \
                     "mbarrier.try_wait.parity.acquire.cta.shared::cta.b64 P1, [%0], %1, 0x989680; " \
                     "@P1 bra.uni WD_%=; bra.uni WL_%=; WD_%=: }"                        \
                     :: "r"(_m), "r"(_p) : "memory");                                    \
    }                                                                                    \
} while (0)

#define BULK_CP(dst_smem, src_gmem, bytes, mbar) \
    asm volatile("cp.async.bulk.shared::cluster.global.mbarrier::complete_tx::bytes " \
                 "[%0], [%1], %2, [%3];" \
                 :: "r"((uint32_t)(dst_smem)), "l"(src_gmem), "r"((uint32_t)(bytes)), \
                    "r"((uint32_t)(mbar)) : "memory")

#if HAS_TCGEN05
#define TCGEN05_ALLOC(smem_addr, nCols) \
    asm volatile("tcgen05.alloc.cta_group::1.sync.aligned.shared::cta.b32 [%0], %1;" \
                 :: "r"((uint32_t)(smem_addr)), "r"((uint32_t)(nCols)) : "memory")
#define TCGEN05_DEALLOC(tmem_addr, nCols) \
    asm volatile("tcgen05.dealloc.cta_group::1.sync.aligned.b32 %0, %1;" \
                 :: "r"(tmem_addr), "r"((uint32_t)(nCols)))
#define TCGEN05_RELINQUISH() \
    asm volatile("tcgen05.relinquish_alloc_permit.cta_group::1.sync.aligned;")
#define TCGEN05_COMMIT(mbar) \
    asm volatile("tcgen05.commit.cta_group::1.mbarrier::arrive::one.shared::cluster.b64 [%0];" \
                 :: "r"((uint32_t)(mbar)) : "memory")
#define TCGEN05_FENCE_AFTER() \
    asm volatile("tcgen05.fence::after_thread_sync;" ::: "memory")
#define TCGEN05_FENCE_BEFORE() \
    asm volatile("tcgen05.fence::before_thread_sync;" ::: "memory")
#define TCGEN05_WAIT_LD() \
    asm volatile("tcgen05.wait::ld.sync.aligned;" ::: "memory")
#define TCGEN05_WAIT_ST() \
    asm volatile("tcgen05.wait::st.sync.aligned;" ::: "memory")

#define TCGEN05_LD_32X32B_X32(r, tmem_addr) \
    asm volatile( \
        "tcgen05.ld.sync.aligned.32x32b.x32.b32 " \
        "{%0, %1, %2, %3, %4, %5, %6, %7, " \
        " %8, %9, %10, %11, %12, %13, %14, %15, " \
        " %16, %17, %18, %19, %20, %21, %22, %23, " \
        " %24, %25, %26, %27, %28, %29, %30, %31}, [%32];" \
        : "=r"((r)[0]),  "=r"((r)[1]),  "=r"((r)[2]),  "=r"((r)[3]), \
          "=r"((r)[4]),  "=r"((r)[5]),  "=r"((r)[6]),  "=r"((r)[7]), \
          "=r"((r)[8]),  "=r"((r)[9]),  "=r"((r)[10]), "=r"((r)[11]), \
          "=r"((r)[12]), "=r"((r)[13]), "=r"((r)[14]), "=r"((r)[15]), \
          "=r"((r)[16]), "=r"((r)[17]), "=r"((r)[18]), "=r"((r)[19]), \
          "=r"((r)[20]), "=r"((r)[21]), "=r"((r)[22]), "=r"((r)[23]), \
          "=r"((r)[24]), "=r"((r)[25]), "=r"((r)[26]), "=r"((r)[27]), \
          "=r"((r)[28]), "=r"((r)[29]), "=r"((r)[30]), "=r"((r)[31]) \
        : "r"(tmem_addr))

#define TCGEN05_ST_32X32B_X32(tmem_addr, r) \
    asm volatile( \
        "tcgen05.st.sync.aligned.32x32b.x32.b32 [%0], " \
        "{%1, %2, %3, %4, %5, %6, %7, %8, " \
        " %9, %10, %11, %12, %13, %14, %15, %16, " \
        " %17, %18, %19, %20, %21, %22, %23, %24, " \
        " %25, %26, %27, %28, %29, %30, %31, %32};" \
        :: "r"(tmem_addr), \
           "r"((r)[0]),  "r"((r)[1]),  "r"((r)[2]),  "r"((r)[3]), \
           "r"((r)[4]),  "r"((r)[5]),  "r"((r)[6]),  "r"((r)[7]), \
           "r"((r)[8]),  "r"((r)[9]),  "r"((r)[10]), "r"((r)[11]), \
           "r"((r)[12]), "r"((r)[13]), "r"((r)[14]), "r"((r)[15]), \
           "r"((r)[16]), "r"((r)[17]), "r"((r)[18]), "r"((r)[19]), \
           "r"((r)[20]), "r"((r)[21]), "r"((r)[22]), "r"((r)[23]), \
           "r"((r)[24]), "r"((r)[25]), "r"((r)[26]), "r"((r)[27]), \
           "r"((r)[28]), "r"((r)[29]), "r"((r)[30]), "r"((r)[31]) \
        : "memory")

__device__ __forceinline__ void mma_f16_ss(uint32_t d_tmem, uint64_t a_desc, uint64_t b_desc,
                                           uint32_t idesc, uint32_t enable) {
    asm volatile(
        "{\n\t"
        ".reg .pred p;\n\t"
        "setp.ne.u32 p, %4, 0;\n\t"
        "tcgen05.mma.cta_group::1.kind::f16 [%0], %1, %2, %3, {%5, %5, %5, %5}, p;\n\t"
        "}"
        :: "r"(d_tmem), "l"(a_desc), "l"(b_desc), "r"(idesc), "r"(enable), "r"(0u)
        : "memory");
}
__device__ __forceinline__ void mma_f16_ts(uint32_t d_tmem, uint32_t a_tmem, uint64_t b_desc,
                                           uint32_t idesc, uint32_t enable) {
    asm volatile(
        "{\n\t"
        ".reg .pred p;\n\t"
        "setp.ne.u32 p, %4, 0;\n\t"
        "tcgen05.mma.cta_group::1.kind::f16 [%0], [%1], %2, %3, {%5, %5, %5, %5}, p;\n\t"
        "}"
        :: "r"(d_tmem), "r"(a_tmem), "l"(b_desc), "r"(idesc), "r"(enable), "r"(0u)
        : "memory");
}
#endif  // HAS_TCGEN05

__device__ __forceinline__ void split_bf16(float f, __nv_bfloat16& h, __nv_bfloat16& l) {
    h = __float2bfloat16(f);
    l = __float2bfloat16(f - __bfloat162float(h));
}

// ============================================================
// Merged split+pack: x (seg 0) and W0..W3 (segs 1..4) in ONE launch.
// ============================================================
#define XN8 (M_TOK * D_MODEL / 8)        // 1048576
#define WN8 (D_MODEL * D_MODEL / 8)      // 524288

__global__ __launch_bounds__(256) void split_all(
    const float* __restrict__ x, const float* __restrict__ W0,
    const float* __restrict__ W1, const float* __restrict__ W2,
    const float* __restrict__ W3)
{
    int i = blockIdx.x * blockDim.x + threadIdx.x;
    const float* src;
    __nv_bfloat16 *hi, *lo;
    int nrt, li;
    if (i < XN8) {
        src = x; hi = g_xh; lo = g_xl; nrt = 32; li = i;
    } else {
        int w = (i - XN8) >> 19;          // / WN8 (2^19)
        li = (i - XN8) & (WN8 - 1);
        src = (w == 0) ? W0 : (w == 1) ? W1 : (w == 2) ? W2 : W3;
        hi = g_wh[w]; lo = g_wl[w]; nrt = 16;
    }
    int elem = li * 8;
    int row = elem >> 11;
    int col = elem & 2047;
    int rt = row >> 7, r = row & 127;
    int c  = col >> 6, kc = col & 63;
    size_t tb = ((size_t)(c * nrt + rt)) << 14;
    uint32_t so = SMEM_SWIZZLE_128B((uint32_t)(r * 128 + kc * 2));

    float4 v0 = ((const float4*)src)[(size_t)li * 2];
    float4 v1 = ((const float4*)src)[(size_t)li * 2 + 1];
    float f[8] = {v0.x, v0.y, v0.z, v0.w, v1.x, v1.y, v1.z, v1.w};
    __align__(16) __nv_bfloat16 h[8], l[8];
#pragma unroll
    for (int j = 0; j < 8; j++) split_bf16(f[j], h[j], l[j]);
    *(uint4*)((char*)hi + tb + so) = *(uint4*)h;
    *(uint4*)((char*)lo + tb + so) = *(uint4*)l;
}

// split+pack for ctx only (after attention)
__global__ __launch_bounds__(256) void split_ctx()
{
    int i = blockIdx.x * blockDim.x + threadIdx.x;
    int elem = i * 8;
    int row = elem >> 11;
    int col = elem & 2047;
    int rt = row >> 7, r = row & 127;
    int c  = col >> 6, kc = col & 63;
    size_t tb = ((size_t)(c * 32 + rt)) << 14;
    uint32_t so = SMEM_SWIZZLE_128B((uint32_t)(r * 128 + kc * 2));

    float4 v0 = ((const float4*)g_ctx)[(size_t)i * 2];
    float4 v1 = ((const float4*)g_ctx)[(size_t)i * 2 + 1];
    float f[8] = {v0.x, v0.y, v0.z, v0.w, v1.x, v1.y, v1.z, v1.w};
    __align__(16) __nv_bfloat16 h[8], l[8];
#pragma unroll
    for (int j = 0; j < 8; j++) split_bf16(f[j], h[j], l[j]);
    *(uint4*)((char*)g_chh + tb + so) = *(uint4*)h;
    *(uint4*)((char*)g_cll + tb + so) = *(uint4*)l;
}

// ============================================================
// Merged attention operand packer: blockIdx.y = 0(Q) / 1(K) / 2(V^T)
// ============================================================
__global__ __launch_bounds__(256) void pack_attn()
{
    int i = blockIdx.x * blockDim.x + threadIdx.x;
    int which = blockIdx.y;
    int elem = i * 8;
    int tok = elem >> 11, col = elem & 2047;
    int b = tok >> 11, s = tok & 2047;
    int h = col >> 7, d = col & 127;
    int bh = b * 16 + h;

    if (which == 0) {
        int rt = s >> 7, r = s & 127, ch = d >> 6, kc = d & 63;
        size_t tb = ((size_t)(((bh * 16 + rt) * 2) + ch)) << 14;
        uint32_t so = SMEM_SWIZZLE_128B((uint32_t)(r * 128 + kc * 2));
        const float* src = g_q + (size_t)tok * 2048 + col;
        float4 v0 = *(const float4*)src, v1 = *(const float4*)(src + 4);
        float f[8] = {v0.x, v0.y, v0.z, v0.w, v1.x, v1.y, v1.z, v1.w};
        __align__(16) __nv_bfloat16 hh[8], ll[8];
#pragma unroll
        for (int j = 0; j < 8; j++) split_bf16(f[j], hh[j], ll[j]);
        *(uint4*)((char*)g_aqh + tb + so) = *(uint4*)hh;
        *(uint4*)((char*)g_aql + tb + so) = *(uint4*)ll;
    } else if (which == 1) {
        int kt = s >> 6, r = s & 63, ch = d >> 6, kc = d & 63;
        size_t tb = ((size_t)(((bh * 32 + kt) * 2) + ch)) << 13;
        uint32_t so = SMEM_SWIZZLE_128B((uint32_t)(r * 128 + kc * 2));
        const float* src = g_k + (size_t)tok * 2048 + col;
        float4 v0 = *(const float4*)src, v1 = *(const float4*)(src + 4);
        float f[8] = {v0.x, v0.y, v0.z, v0.w, v1.x, v1.y, v1.z, v1.w};
        __align__(16) __nv_bfloat16 hh[8], ll[8];
#pragma unroll
        for (int j = 0; j < 8; j++) split_bf16(f[j], hh[j], ll[j]);
        *(uint4*)((char*)g_akh + tb + so) = *(uint4*)hh;
        *(uint4*)((char*)g_akl + tb + so) = *(uint4*)ll;
    } else {
        int kt = s >> 6, sc = s & 63;
        size_t tb = ((size_t)(bh * 32 + kt)) << 14;
        const float* src = g_v + (size_t)tok * 2048 + col;
        float4 v0 = *(const float4*)src, v1 = *(const float4*)(src + 4);
        float f[8] = {v0.x, v0.y, v0.z, v0.w, v1.x, v1.y, v1.z, v1.w};
#pragma unroll
        for (int j = 0; j < 8; j++) {
            __nv_bfloat16 hh, ll;
            split_bf16(f[j], hh, ll);
            uint32_t off = SMEM_SWIZZLE_128B((uint32_t)((d + j) * 128 + sc * 2));
            *(__nv_bfloat16*)((char*)g_avh + tb + off) = hh;
            *(__nv_bfloat16*)((char*)g_avl + tb + off) = ll;
        }
    }
}

// ============================================================
// tcgen05 GEMM (NT), unchanged.
// ============================================================
#define NCH  32
#define NRT_A 32
#define NRT_W 16
#define TIL  16384
#define STG  (6 * TIL)
#define SMB0 1024
#define GEMM_SMEM (SMB0 + 2 * STG)
#define GEMM_IDESC 0x8400490u

__global__ __launch_bounds__(256) void gemm_tc(
    int mode_base, const float* __restrict__ b0, const float* __restrict__ b1,
    const float* __restrict__ b2, const float* __restrict__ b3,
    float* __restrict__ out)
{
#if HAS_TCGEN05
    extern __shared__ char sm[];
    const uint32_t smb = smem_u32(sm);
    const int tid = threadIdx.x;
    const int wid = tid >> 5;
    const int lid = tid & 31;
    const int rm = blockIdx.y;
    const int bx = blockIdx.x;
    const int mode = mode_base + blockIdx.z;

    const __nv_bfloat16* Ah = (mode < 3) ? g_xh : g_chh;
    const __nv_bfloat16* Al = (mode < 3) ? g_xl : g_cll;
    const __nv_bfloat16* Bh = g_wh[mode];
    const __nv_bfloat16* Bl = g_wl[mode];
    const float* bias = (mode == 0) ? b0 : (mode == 1) ? b1 : (mode == 2) ? b2 : b3;
    const float alpha = (mode == 0) ? 0.08838834764831845f : 1.0f;
    float* C = (mode == 0) ? g_q : (mode == 1) ? g_k : (mode == 2) ? g_v : out;

    if (wid == 0) TCGEN05_ALLOC(smb + 0, 256);
    if (tid == 0) {
#pragma unroll
        for (int s = 0; s < 2; ++s) {
            MBARRIER_INIT(smb + 64 + 16 * s, 1);
            MBARRIER_INIT(smb + 96 + 16 * s, 1);
        }
    }
    __syncthreads();

    uint32_t tmem;
    asm volatile("ld.shared.b32 %0, [%1];" : "=r"(tmem) : "r"(smb + 0));

    if (wid == 0 && elect_one_pred()) {
#define LOAD_CHUNK(c, s)                                                        \
        do {                                                                    \
            uint32_t st = smb + SMB0 + (s) * STG;                               \
            uint32_t fb = smb + 64 + 16 * (s);                                  \
            size_t ao = ((size_t)((c) * NRT_A + rm)) << 14;                     \
            size_t bo = ((size_t)((c) * NRT_W + 2 * bx)) << 14;                 \
            MBARRIER_EXPECT_TX(fb, 6 * TIL);                                    \
            BULK_CP(st,           (const char*)Ah + ao, TIL,     fb);           \
            BULK_CP(st + TIL,     (const char*)Al + ao, TIL,     fb);           \
            BULK_CP(st + 2 * TIL, (const char*)Bh + bo, 2 * TIL, fb);           \
            BULK_CP(st + 4 * TIL, (const char*)Bl + bo, 2 * TIL, fb);           \
        } while (0)

        LOAD_CHUNK(0, 0);
        LOAD_CHUNK(1, 1);

        for (int c = 0; c < NCH; ++c) {
            int s = c & 1, ph = (c >> 1) & 1;
            uint32_t st = smb + SMB0 + s * STG;
            MBARRIER_WAIT_PARITY(smb + 64 + 16 * s, ph);
            uint64_t dAh = MAKE_SMEM_DESC(st);
            uint64_t dAl = MAKE_SMEM_DESC(st + TIL);
            uint64_t dBh = MAKE_SMEM_DESC(st + 2 * TIL);
            uint64_t dBl = MAKE_SMEM_DESC(st + 4 * TIL);
#pragma unroll
            for (int ks = 0; ks < 4; ++ks) {
                mma_f16_ss(tmem, dAh + ks * 2, dBh + ks * 2, GEMM_IDESC, (c | ks) != 0);
                mma_f16_ss(tmem, dAl + ks * 2, dBh + ks * 2, GEMM_IDESC, 1);
                mma_f16_ss(tmem, dAh + ks * 2, dBl + ks * 2, GEMM_IDESC, 1);
            }
            TCGEN05_COMMIT(smb + 96 + 16 * s);
            if (c + 2 < NCH) {
                MBARRIER_WAIT_PARITY(smb + 96 + 16 * s, ph);
                LOAD_CHUNK(c + 2, s);
            }
        }
        MBARRIER_WAIT_PARITY(smb + 96 + 16 * ((NCH - 1) & 1), ((NCH - 1) >> 1) & 1);
#undef LOAD_CHUNK
    }
    __syncthreads();
    TCGEN05_FENCE_AFTER();

    const int wg = wid >> 2;
    const int sub = wid & 3;
    const int m = blockIdx.y * 128 + sub * 32 + lid;
    float* crow = C + (size_t)m * D_MODEL;
#pragma unroll
    for (int cb = 0; cb < 4; ++cb) {
        uint32_t r[32];
        TCGEN05_LD_32X32B_X32(r, tmem + wg * 128 + cb * 32);
        TCGEN05_WAIT_LD();
        int n0 = bx * 256 + wg * 128 + cb * 32;
#pragma unroll
        for (int j = 0; j < 32; j += 4) {
            float4 o;
            o.x = (__uint_as_float(r[j + 0]) + bias[n0 + j + 0]) * alpha;
            o.y = (__uint_as_float(r[j + 1]) + bias[n0 + j + 1]) * alpha;
            o.z = (__uint_as_float(r[j + 2]) + bias[n0 + j + 2]) * alpha;
            o.w = (__uint_as_float(r[j + 3]) + bias[n0 + j + 3]) * alpha;
            *(float4*)(crow + n0 + j) = o;
        }
    }
    TCGEN05_FENCE_BEFORE();

    __syncthreads();
    if (tid == 0) {
#pragma unroll
        for (int s = 0; s < 2; ++s) {
            MBARRIER_INVAL(smb + 64 + 16 * s);
            MBARRIER_INVAL(smb + 96 + 16 * s);
        }
    }
    __syncthreads();
    if (wid == 0) {
        TCGEN05_RELINQUISH();
        TCGEN05_DEALLOC(tmem, 256);
    }
#endif
}

// ============================================================
// tcgen05 flash attention v2 (fixed): Q in TMEM (TS S-MMA),
// K 2-stage, V 4-stage smem -> loads 2 iters ahead.
// ============================================================
#define AOFF_MASK 1024
#define AOFF_K    9216              // 2 stages x 32KB (Kh|Kl)
#define AOFF_V    74752             // 4 stages x 32KB (Vh|Vl)
#define AOFF_QS   (AOFF_V + 65536)  // Q staging overlays V stages 2,3
#define ATTN_SMEM 205824
#define IDESC_S   0x8100490u
#define IDESC_PV  0x8200490u

__global__ __launch_bounds__(160) void attn_tc(const float* __restrict__ mask)
{
#if HAS_TCGEN05
    extern __shared__ char sm[];
    const uint32_t smb = smem_u32(sm);
    const int tid = threadIdx.x;
    const int wid = tid >> 5;
    const int lid = tid & 31;
    const int rt = blockIdx.x;
    const int bh = blockIdx.y;
    const int b = bh >> 4;

    if (wid == 0) TCGEN05_ALLOC(smb + 0, 512);
    if (tid == 0) {
        MBARRIER_INIT(smb + 64, 1);    // qbar (tx)
        MBARRIER_INIT(smb + 80, 4);    // qdone
#pragma unroll
        for (int s = 0; s < 2; ++s) {
            MBARRIER_INIT(smb + 96 + 16 * s, 1);    // full (tx)
            MBARRIER_INIT(smb + 128 + 16 * s, 1);   // s_full (commit)
            MBARRIER_INIT(smb + 160 + 16 * s, 4);   // smax_free
            MBARRIER_INIT(smb + 192 + 16 * s, 4);   // p_ready
            MBARRIER_INIT(smb + 224 + 16 * s, 1);   // pv_done (commit)
        }
    }
    for (int j = tid; j < SEQ; j += 160) {
        float mv = mask[b * SEQ + j];
        ((float*)(sm + AOFF_MASK))[j] = (1.0f - mv) * -1e30f;
    }
    __syncthreads();

    uint32_t tmem;
    asm volatile("ld.shared.b32 %0, [%1];" : "=r"(tmem) : "r"(smb + 0));

    // ---------------- control warp ----------------
    if (wid == 4) {
        if (elect_one_pred()) {
#define LOADKV(c)                                                          \
            do {                                                           \
                size_t kb = ((size_t)(bh * 32 + (c))) << 14;               \
                uint32_t kst = smb + AOFF_K + ((c) & 1) * 32768;           \
                uint32_t vst = smb + AOFF_V + ((c) & 3) * 32768;           \
                uint32_t fb = smb + 96 + 16 * ((c) & 1);                   \
                MBARRIER_EXPECT_TX(fb, 65536);                             \
                BULK_CP(kst,         (const char*)g_akh + kb, 16384, fb);  \
                BULK_CP(kst + 16384, (const char*)g_akl + kb, 16384, fb);  \
                BULK_CP(vst,         (const char*)g_avh + kb, 16384, fb);  \
                BULK_CP(vst + 16384, (const char*)g_avl + kb, 16384, fb);  \
            } while (0)

            // prologue: Q into staging (V stages 2,3 area) + chunks 0,1
            {
                size_t qb = ((size_t)(bh * 16 + rt)) << 15;
                MBARRIER_EXPECT_TX(smb + 64, 65536);
                BULK_CP(smb + AOFF_QS,         (const char*)g_aqh + qb, 32768, smb + 64);
                BULK_CP(smb + AOFF_QS + 32768, (const char*)g_aql + qb, 32768, smb + 64);
                LOADKV(0);
                LOADKV(1);
            }
            // wait for Q to land in TMEM (softmax warps copy it)
            MBARRIER_WAIT_PARITY(smb + 80, 0);
            TCGEN05_FENCE_AFTER();

            const uint32_t qh = tmem + 384, ql = tmem + 448;

            for (int i = 0; i < 32; ++i) {
                const int sb = i & 1;
                // S(i)
                MBARRIER_WAIT_PARITY(smb + 96 + 16 * sb, (i >> 1) & 1);       // full
                if (i >= 2) MBARRIER_WAIT_PARITY(smb + 160 + 16 * sb, ((i - 2) >> 1) & 1);
                {
                    uint32_t kst = smb + AOFF_K + sb * 32768;
                    uint32_t sreg = tmem + sb * 64;
#pragma unroll
                    for (int st = 0; st < 8; ++st) {
                        uint64_t bh_ = MAKE_SMEM_DESC(kst + (st >> 2) * 8192) + (st & 3) * 2;
                        uint64_t bl_ = MAKE_SMEM_DESC(kst + 16384 + (st >> 2) * 8192) + (st & 3) * 2;
                        mma_f16_ts(sreg, qh + st * 8, bh_, IDESC_S, st != 0);
                        mma_f16_ts(sreg, ql + st * 8, bh_, IDESC_S, 1);
                        mma_f16_ts(sreg, qh + st * 8, bl_, IDESC_S, 1);
                    }
                    TCGEN05_COMMIT(smb + 128 + 16 * sb);
                }
                // PV(i-1)
                if (i >= 1) {
                    const int j = i - 1, pb = j & 1, pj = (j >> 1) & 1;
                    MBARRIER_WAIT_PARITY(smb + 192 + 16 * pb, pj);
                    TCGEN05_FENCE_AFTER();
                    uint32_t vst = smb + AOFF_V + (j & 3) * 32768;
                    uint64_t dVh = MAKE_SMEM_DESC(vst);
                    uint64_t dVl = MAKE_SMEM_DESC(vst + 16384);
#pragma unroll
                    for (int ks = 0; ks < 4; ++ks) {
                        uint32_t ah = tmem + 256 + pb * 64 + ks * 8;
                        uint32_t al = tmem + 288 + pb * 64 + ks * 8;
                        mma_f16_ts(tmem + 128, ah, dVh + ks * 2, IDESC_PV, (j | ks) != 0);
                        mma_f16_ts(tmem + 128, al, dVh + ks * 2, IDESC_PV, 1);
                        mma_f16_ts(tmem + 128, ah, dVl + ks * 2, IDESC_PV, 1);
                    }
                    TCGEN05_COMMIT(smb + 224 + 16 * pb);
                }
                // load chunk i+2 (K stage freed by s_full(i); V stage freed by pv_done(i-2))
                if (i <= 29) {
                    MBARRIER_WAIT_PARITY(smb + 128 + 16 * sb, (i >> 1) & 1);  // s_full(i)
                    if (i >= 2)
                        MBARRIER_WAIT_PARITY(smb + 224 + 16 * (i & 1), ((i - 2) >> 1) & 1);
                    LOADKV(i + 2);
                }
            }
            // final PV: j = 31, then wait all MMAs done
            {
                const int j = 31, pb = 1, pj = 1;
                MBARRIER_WAIT_PARITY(smb + 192 + 16 * pb, pj);
                TCGEN05_FENCE_AFTER();
                uint32_t vst = smb + AOFF_V + (j & 3) * 32768;
                uint64_t dVh = MAKE_SMEM_DESC(vst);
                uint64_t dVl = MAKE_SMEM_DESC(vst + 16384);
#pragma unroll
                for (int ks = 0; ks < 4; ++ks) {
                    uint32_t ah = tmem + 256 + pb * 64 + ks * 8;
                    uint32_t al = tmem + 288 + pb * 64 + ks * 8;
                    mma_f16_ts(tmem + 128, ah, dVh + ks * 2, IDESC_PV, 1);
                    mma_f16_ts(tmem + 128, al, dVh + ks * 2, IDESC_PV, 1);
                    mma_f16_ts(tmem + 128, ah, dVl + ks * 2, IDESC_PV, 1);
                }
                TCGEN05_COMMIT(smb + 224 + 16 * pb);
                MBARRIER_WAIT_PARITY(smb + 224 + 16 * pb, pj);
            }
#undef LOADKV
        }
    }

    // ---------------- softmax warps ----------------
    float l = 0.0f;
    if (wid < 4) {
        const uint32_t wo = (uint32_t)wid << 21;
        // Q prologue: smem staging -> TMEM (hi then lo, 32-col pieces)
        MBARRIER_WAIT_PARITY(smb + 64, 0);
        {
            const int r = wid * 32 + lid;
#pragma unroll
            for (int part = 0; part < 4; ++part) {       // part: 0,1 = hi ch0/ch1; 2,3 = lo
                uint32_t base = AOFF_QS + (part >> 1) * 32768 + (part & 1) * 16384;
                uint32_t q32[32];
#pragma unroll
                for (int g = 0; g < 8; ++g) {
                    uint32_t off = base + SMEM_SWIZZLE_128B((uint32_t)(r * 128 + g * 16));
                    uint4 v = *(const uint4*)(sm + off);
                    q32[g * 4 + 0] = v.x; q32[g * 4 + 1] = v.y;
                    q32[g * 4 + 2] = v.z; q32[g * 4 + 3] = v.w;
                }
                uint32_t dst = tmem + 384 + (part >> 1) * 64 + (part & 1) * 32 + wo;
                TCGEN05_ST_32X32B_X32(dst, q32);
            }
            TCGEN05_WAIT_ST();
            TCGEN05_FENCE_BEFORE();
            if (elect_one_pred()) MBARRIER_ARRIVE(smb + 80);   // qdone
        }

        const float* md_base = (const float*)(sm + AOFF_MASK);
        for (int i = 0; i < 32; ++i) {
            int s = i & 1, ph = (i >> 1) & 1;
            MBARRIER_WAIT_PARITY(smb + 128 + 16 * s, ph);      // s_full
            TCGEN05_FENCE_AFTER();
            uint32_t r0[32], r1[32];
            TCGEN05_LD_32X32B_X32(r0, tmem + s * 64);
            TCGEN05_LD_32X32B_X32(r1, tmem + s * 64 + 32);
            TCGEN05_WAIT_LD();
            if (elect_one_pred()) MBARRIER_ARRIVE(smb + 160 + 16 * s);  // smax_free

            const float* md = md_base + i * 64;
#pragma unroll
            for (int j = 0; j < 32; ++j) {
                float e = __expf(__uint_as_float(r0[j]) + md[j]);
                l += e;
                r0[j] = __float_as_uint(e);
            }
#pragma unroll
            for (int j = 0; j < 32; ++j) {
                float e = __expf(__uint_as_float(r1[j]) + md[32 + j]);
                l += e;
                r1[j] = __float_as_uint(e);
            }
            uint32_t phv[32], plv[32];
#pragma unroll
            for (int p = 0; p < 16; ++p) {
                __nv_bfloat16 h0, h1, l0, l1;
                split_bf16(__uint_as_float(r0[2 * p]), h0, l0);
                split_bf16(__uint_as_float(r0[2 * p + 1]), h1, l1);
                __nv_bfloat162 hp(h0, h1), lp(l0, l1);
                phv[p] = *(uint32_t*)&hp;
                plv[p] = *(uint32_t*)&lp;
            }
#pragma unroll
            for (int p = 0; p < 16; ++p) {
                __nv_bfloat16 h0, h1, l0, l1;
                split_bf16(__uint_as_float(r1[2 * p]), h0, l0);
                split_bf16(__uint_as_float(r1[2 * p + 1]), h1, l1);
                __nv_bfloat162 hp(h0, h1), lp(l0, l1);
                phv[16 + p] = *(uint32_t*)&hp;
                plv[16 + p] = *(uint32_t*)&lp;
            }
            TCGEN05_ST_32X32B_X32(tmem + 256 + s * 64 + wo, phv);
            TCGEN05_ST_32X32B_X32(tmem + 288 + s * 64 + wo, plv);
            TCGEN05_WAIT_ST();
            TCGEN05_FENCE_BEFORE();
            if (elect_one_pred()) MBARRIER_ARRIVE(smb + 192 + 16 * s);  // p_ready
        }
    }

    __syncthreads();

    // epilogue: normalize O and write ctx
    if (wid < 4) {
        TCGEN05_FENCE_AFTER();
        float inv = 1.0f / l;
        int qrow = rt * 128 + wid * 32 + lid;
        float* dst = g_ctx + ((size_t)(b * SEQ + qrow)) * D_MODEL + (bh & 15) * HDIM;
#pragma unroll
        for (int cb = 0; cb < 4; ++cb) {
            uint32_t r[32];
            TCGEN05_LD_32X32B_X32(r, tmem + 128 + cb * 32);
            TCGEN05_WAIT_LD();
#pragma unroll
            for (int j = 0; j < 32; j += 4) {
                float4 o;
                o.x = __uint_as_float(r[j + 0]) * inv;
                o.y = __uint_as_float(r[j + 1]) * inv;
                o.z = __uint_as_float(r[j + 2]) * inv;
                o.w = __uint_as_float(r[j + 3]) * inv;
                *(float4*)(dst + cb * 32 + j) = o;
            }
        }
        TCGEN05_FENCE_BEFORE();
    }

    __syncthreads();
    if (tid == 0) {
        MBARRIER_INVAL(smb + 64);
        MBARRIER_INVAL(smb + 80);
#pragma unroll
        for (int s = 0; s < 2; ++s) {
            MBARRIER_INVAL(smb + 96 + 16 * s);
            MBARRIER_INVAL(smb + 128 + 16 * s);
            MBARRIER_INVAL(smb + 160 + 16 * s);
            MBARRIER_INVAL(smb + 192 + 16 * s);
            MBARRIER_INVAL(smb + 224 + 16 * s);
        }
    }
    __syncthreads();
    if (wid == 0) {
        TCGEN05_RELINQUISH();
        TCGEN05_DEALLOC(tmem, 512);
    }
#endif  // HAS_TCGEN05
}

// ============================================================
extern "C" void kernel_launch(void* const* d_in, const int* in_sizes, int n_in,
                              void* d_out, int out_size)
{
    const float* x    = (const float*)d_in[0];
    const float* mask = (const float*)d_in[1];
    const float* Wq   = (const float*)d_in[2];
    const float* bq   = (const float*)d_in[3];
    const float* Wk   = (const float*)d_in[4];
    const float* bk   = (const float*)d_in[5];
    const float* Wv   = (const float*)d_in[6];
    const float* bv   = (const float*)d_in[7];
    const float* Wo   = (const float*)d_in[8];
    const float* bo   = (const float*)d_in[9];
    float* out = (float*)d_out;

    const int XN = M_TOK * D_MODEL;
    const int TOTAL8 = XN8 + 4 * WN8;

    cudaFuncSetAttribute(gemm_tc, cudaFuncAttributeMaxDynamicSharedMemorySize, GEMM_SMEM);
    cudaFuncSetAttribute(attn_tc, cudaFuncAttributeMaxDynamicSharedMemorySize, ATTN_SMEM);

    split_all<<<TOTAL8 / 256, 256>>>(x, Wq, Wk, Wv, Wo);
    gemm_tc<<<dim3(8, 32, 3), 256, GEMM_SMEM>>>(0, bq, bk, bv, bo, out);
    pack_attn<<<dim3(XN / 8 / 256, 3), 256>>>();
    attn_tc<<<dim3(16, 32), 160, ATTN_SMEM>>>(mask);
    split_ctx<<<XN / 8 / 256, 256>>>();
    gemm_tc<<<dim3(8, 32, 1), 256, GEMM_SMEM>>>(3, bq, bk, bv, bo, out);
}

// round 10
// speedup vs baseline: 1.5158x; 1.0423x over previous
#include <cuda_runtime.h>
#include <cuda_bf16.h>
#include <cstdint>

#define D_MODEL 2048
#define SEQ     2048
#define BATCH   2
#define NHEADS  16
#define HDIM    128
#define M_TOK   (BATCH*SEQ)   // 4096

#if defined(__CUDA_ARCH_FEAT_SM103_ALL) || defined(__CUDA_ARCH_FEAT_SM100_ALL) || \
    (defined(__CUDA_ARCH_SPECIFIC__) && (__CUDA_ARCH_SPECIFIC__ >= 1000))
#define HAS_TCGEN05 1
#else
#define HAS_TCGEN05 0
#endif

// ---- persistent scratch ----
__device__ float g_v[M_TOK * D_MODEL];     // fp32 V (packed to V^T by pack_v)

__device__ __nv_bfloat16 g_xh[M_TOK * D_MODEL];
__device__ __nv_bfloat16 g_xl[M_TOK * D_MODEL];
__device__ __nv_bfloat16 g_chh[M_TOK * D_MODEL];   // packed ctx (written by attn)
__device__ __nv_bfloat16 g_cll[M_TOK * D_MODEL];
__device__ __nv_bfloat16 g_wh[4][D_MODEL * D_MODEL];
__device__ __nv_bfloat16 g_wl[4][D_MODEL * D_MODEL];

__device__ __nv_bfloat16 g_aqh[M_TOK * D_MODEL];   // Q tiles: [bh][rt16][2ch x 16KB]
__device__ __nv_bfloat16 g_aql[M_TOK * D_MODEL];
__device__ __nv_bfloat16 g_akh[M_TOK * D_MODEL];   // K tiles: [bh][kt32][2ch x 8KB]
__device__ __nv_bfloat16 g_akl[M_TOK * D_MODEL];
__device__ __nv_bfloat16 g_avh[M_TOK * D_MODEL];   // V^T tiles: [bh][kt32][16KB]
__device__ __nv_bfloat16 g_avl[M_TOK * D_MODEL];

// ============================================================
// PTX helpers
// ============================================================
__device__ __forceinline__ uint32_t smem_u32(const void* p) {
    uint32_t a;
    asm("{ .reg .u64 t; cvta.to.shared.u64 t, %1; cvt.u32.u64 %0, t; }" : "=r"(a) : "l"(p));
    return a;
}
__device__ __forceinline__ uint32_t elect_one_pred() {
    uint32_t p;
    asm volatile("{ .reg .pred p; elect.sync _|p, 0xFFFFFFFF; selp.b32 %0, 1, 0, p; }" : "=r"(p));
    return p;
}
static constexpr uint64_t SMEM_DESC_BASE_SW128 =
    (uint64_t(2) << 61) | (uint64_t(1) << 46) | (uint64_t(64) << 32) | (uint64_t(1) << 16);
#define MAKE_SMEM_DESC(base_addr) \
    (SMEM_DESC_BASE_SW128 | ((uint64_t)((base_addr) >> 4) & 0x3FFF))
#define SMEM_SWIZZLE_128B(off) ((off) ^ (((off) >> 3) & 0x70))

#define MBARRIER_INIT(mbar, count) \
    asm volatile("mbarrier.init.shared.b64 [%0], %1;" \
                 :: "r"((uint32_t)(mbar)), "r"((uint32_t)(count)) : "memory")
#define MBARRIER_INVAL(mbar) \
    asm volatile("mbarrier.inval.shared.b64 [%0];" :: "r"((uint32_t)(mbar)) : "memory")
#define MBARRIER_EXPECT_TX(mbar, bytes) \
    asm volatile("mbarrier.arrive.expect_tx.shared.b64 _, [%0], %1;" \
                 :: "r"((uint32_t)(mbar)), "r"((uint32_t)(bytes)) : "memory")
#define MBARRIER_ARRIVE(mbar) \
    asm volatile("mbarrier.arrive.shared.b64 _, [%0];" :: "r"((uint32_t)(mbar)) : "memory")
#define MBARRIER_WAIT_PARITY(mbar, parity) do {                                          \
    uint32_t _m = (uint32_t)(mbar);                                                      \
    uint32_t _p = (uint32_t)(parity);                                                    \
    uint32_t _done;                                                                      \
    asm volatile("{ .reg .pred p; mbarrier.try_wait.parity.acquire.cta.shared::cta.b64 " \
                 "p, [%1], %2; selp.b32 %0, 1, 0, p; }"                                  \
                 : "=r"(_done) : "r"(_m), "r"(_p) : "memory");                           \
    if (!_done) {                                                                        \
        asm volatile("{ .reg .pred P1; WL_%=: "                                          \
                     "mbarrier.try_wait.parity.acquire.cta.shared::cta.b64 P1, [%0], %1, 0x989680; " \
                     "@P1 bra.uni WD_%=; bra.uni WL_%=; WD_%=: }"                        \
                     :: "r"(_m), "r"(_p) : "memory");                                    \
    }                                                                                    \
} while (0)

#define BULK_CP(dst_smem, src_gmem, bytes, mbar) \
    asm volatile("cp.async.bulk.shared::cluster.global.mbarrier::complete_tx::bytes " \
                 "[%0], [%1], %2, [%3];" \
                 :: "r"((uint32_t)(dst_smem)), "l"(src_gmem), "r"((uint32_t)(bytes)), \
                    "r"((uint32_t)(mbar)) : "memory")

#if HAS_TCGEN05
#define TCGEN05_ALLOC(smem_addr, nCols) \
    asm volatile("tcgen05.alloc.cta_group::1.sync.aligned.shared::cta.b32 [%0], %1;" \
                 :: "r"((uint32_t)(smem_addr)), "r"((uint32_t)(nCols)) : "memory")
#define TCGEN05_DEALLOC(tmem_addr, nCols) \
    asm volatile("tcgen05.dealloc.cta_group::1.sync.aligned.b32 %0, %1;" \
                 :: "r"(tmem_addr), "r"((uint32_t)(nCols)))
#define TCGEN05_RELINQUISH() \
    asm volatile("tcgen05.relinquish_alloc_permit.cta_group::1.sync.aligned;")
#define TCGEN05_COMMIT(mbar) \
    asm volatile("tcgen05.commit.cta_group::1.mbarrier::arrive::one.shared::cluster.b64 [%0];" \
                 :: "r"((uint32_t)(mbar)) : "memory")
#define TCGEN05_FENCE_AFTER() \
    asm volatile("tcgen05.fence::after_thread_sync;" ::: "memory")
#define TCGEN05_FENCE_BEFORE() \
    asm volatile("tcgen05.fence::before_thread_sync;" ::: "memory")
#define TCGEN05_WAIT_LD() \
    asm volatile("tcgen05.wait::ld.sync.aligned;" ::: "memory")
#define TCGEN05_WAIT_ST() \
    asm volatile("tcgen05.wait::st.sync.aligned;" ::: "memory")

#define TCGEN05_LD_32X32B_X32(r, tmem_addr) \
    asm volatile( \
        "tcgen05.ld.sync.aligned.32x32b.x32.b32 " \
        "{%0, %1, %2, %3, %4, %5, %6, %7, " \
        " %8, %9, %10, %11, %12, %13, %14, %15, " \
        " %16, %17, %18, %19, %20, %21, %22, %23, " \
        " %24, %25, %26, %27, %28, %29, %30, %31}, [%32];" \
        : "=r"((r)[0]),  "=r"((r)[1]),  "=r"((r)[2]),  "=r"((r)[3]), \
          "=r"((r)[4]),  "=r"((r)[5]),  "=r"((r)[6]),  "=r"((r)[7]), \
          "=r"((r)[8]),  "=r"((r)[9]),  "=r"((r)[10]), "=r"((r)[11]), \
          "=r"((r)[12]), "=r"((r)[13]), "=r"((r)[14]), "=r"((r)[15]), \
          "=r"((r)[16]), "=r"((r)[17]), "=r"((r)[18]), "=r"((r)[19]), \
          "=r"((r)[20]), "=r"((r)[21]), "=r"((r)[22]), "=r"((r)[23]), \
          "=r"((r)[24]), "=r"((r)[25]), "=r"((r)[26]), "=r"((r)[27]), \
          "=r"((r)[28]), "=r"((r)[29]), "=r"((r)[30]), "=r"((r)[31]) \
        : "r"(tmem_addr))

#define TCGEN05_ST_32X32B_X32(tmem_addr, r) \
    asm volatile( \
        "tcgen05.st.sync.aligned.32x32b.x32.b32 [%0], " \
        "{%1, %2, %3, %4, %5, %6, %7, %8, " \
        " %9, %10, %11, %12, %13, %14, %15, %16, " \
        " %17, %18, %19, %20, %21, %22, %23, %24, " \
        " %25, %26, %27, %28, %29, %30, %31, %32};" \
        :: "r"(tmem_addr), \
           "r"((r)[0]),  "r"((r)[1]),  "r"((r)[2]),  "r"((r)[3]), \
           "r"((r)[4]),  "r"((r)[5]),  "r"((r)[6]),  "r"((r)[7]), \
           "r"((r)[8]),  "r"((r)[9]),  "r"((r)[10]), "r"((r)[11]), \
           "r"((r)[12]), "r"((r)[13]), "r"((r)[14]), "r"((r)[15]), \
           "r"((r)[16]), "r"((r)[17]), "r"((r)[18]), "r"((r)[19]), \
           "r"((r)[20]), "r"((r)[21]), "r"((r)[22]), "r"((r)[23]), \
           "r"((r)[24]), "r"((r)[25]), "r"((r)[26]), "r"((r)[27]), \
           "r"((r)[28]), "r"((r)[29]), "r"((r)[30]), "r"((r)[31]) \
        : "memory")

__device__ __forceinline__ void mma_f16_ss(uint32_t d_tmem, uint64_t a_desc, uint64_t b_desc,
                                           uint32_t idesc, uint32_t enable) {
    asm volatile(
        "{\n\t"
        ".reg .pred p;\n\t"
        "setp.ne.u32 p, %4, 0;\n\t"
        "tcgen05.mma.cta_group::1.kind::f16 [%0], %1, %2, %3, {%5, %5, %5, %5}, p;\n\t"
        "}"
        :: "r"(d_tmem), "l"(a_desc), "l"(b_desc), "r"(idesc), "r"(enable), "r"(0u)
        : "memory");
}
__device__ __forceinline__ void mma_f16_ts(uint32_t d_tmem, uint32_t a_tmem, uint64_t b_desc,
                                           uint32_t idesc, uint32_t enable) {
    asm volatile(
        "{\n\t"
        ".reg .pred p;\n\t"
        "setp.ne.u32 p, %4, 0;\n\t"
        "tcgen05.mma.cta_group::1.kind::f16 [%0], [%1], %2, %3, {%5, %5, %5, %5}, p;\n\t"
        "}"
        :: "r"(d_tmem), "r"(a_tmem), "l"(b_desc), "r"(idesc), "r"(enable), "r"(0u)
        : "memory");
}
#endif  // HAS_TCGEN05

__device__ __forceinline__ void split_bf16(float f, __nv_bfloat16& h, __nv_bfloat16& l) {
    h = __float2bfloat16(f);
    l = __float2bfloat16(f - __bfloat162float(h));
}

// ============================================================
// Merged split+pack: x (seg 0) and W0..W3 (segs 1..4) in ONE launch.
// ============================================================
#define XN8 (M_TOK * D_MODEL / 8)        // 1048576
#define WN8 (D_MODEL * D_MODEL / 8)      // 524288

__global__ __launch_bounds__(256) void split_all(
    const float* __restrict__ x, const float* __restrict__ W0,
    const float* __restrict__ W1, const float* __restrict__ W2,
    const float* __restrict__ W3)
{
    int i = blockIdx.x * blockDim.x + threadIdx.x;
    const float* src;
    __nv_bfloat16 *hi, *lo;
    int nrt, li;
    if (i < XN8) {
        src = x; hi = g_xh; lo = g_xl; nrt = 32; li = i;
    } else {
        int w = (i - XN8) >> 19;          // / WN8 (2^19)
        li = (i - XN8) & (WN8 - 1);
        src = (w == 0) ? W0 : (w == 1) ? W1 : (w == 2) ? W2 : W3;
        hi = g_wh[w]; lo = g_wl[w]; nrt = 16;
    }
    int elem = li * 8;
    int row = elem >> 11;
    int col = elem & 2047;
    int rt = row >> 7, r = row & 127;
    int c  = col >> 6, kc = col & 63;
    size_t tb = ((size_t)(c * nrt + rt)) << 14;
    uint32_t so = SMEM_SWIZZLE_128B((uint32_t)(r * 128 + kc * 2));

    float4 v0 = ((const float4*)src)[(size_t)li * 2];
    float4 v1 = ((const float4*)src)[(size_t)li * 2 + 1];
    float f[8] = {v0.x, v0.y, v0.z, v0.w, v1.x, v1.y, v1.z, v1.w};
    __align__(16) __nv_bfloat16 h[8], l[8];
#pragma unroll
    for (int j = 0; j < 8; j++) split_bf16(f[j], h[j], l[j]);
    *(uint4*)((char*)hi + tb + so) = *(uint4*)h;
    *(uint4*)((char*)lo + tb + so) = *(uint4*)l;
}

// ============================================================
// V^T packer (scatter-heavy; kept standalone): fp32 g_v -> V^T tiles
// ============================================================
__global__ __launch_bounds__(256) void pack_v()
{
    int i = blockIdx.x * blockDim.x + threadIdx.x;
    int elem = i * 8;
    int tok = elem >> 11, col = elem & 2047;
    int b = tok >> 11, s = tok & 2047;
    int h = col >> 7, d = col & 127;
    int bh = b * 16 + h;
    int kt = s >> 6, sc = s & 63;
    size_t tb = ((size_t)(bh * 32 + kt)) << 14;
    const float* src = g_v + (size_t)tok * 2048 + col;
    float4 v0 = *(const float4*)src, v1 = *(const float4*)(src + 4);
    float f[8] = {v0.x, v0.y, v0.z, v0.w, v1.x, v1.y, v1.z, v1.w};
#pragma unroll
    for (int j = 0; j < 8; j++) {
        __nv_bfloat16 hh, ll;
        split_bf16(f[j], hh, ll);
        uint32_t off = SMEM_SWIZZLE_128B((uint32_t)((d + j) * 128 + sc * 2));
        *(__nv_bfloat16*)((char*)g_avh + tb + off) = hh;
        *(__nv_bfloat16*)((char*)g_avl + tb + off) = ll;
    }
}

// ============================================================
// tcgen05 GEMM (NT). mode = blockIdx.z + mode_base:
//   0 = Q proj (epilogue packs Q attention tiles, alpha=1/sqrt(hd))
//   1 = K proj (epilogue packs K attention tiles)
//   2 = V proj (epilogue writes fp32 g_v)
//   3 = O proj (A = packed ctx; epilogue writes fp32 out)
// Tile 128(M) x 256(N), K-chunk 64 bf16, 3-MMA hi/lo split.
// ============================================================
#define NCH  32
#define NRT_A 32
#define NRT_W 16
#define TIL  16384
#define STG  (6 * TIL)
#define SMB0 1024
#define GEMM_SMEM (SMB0 + 2 * STG)
#define GEMM_IDESC 0x8400490u

__global__ __launch_bounds__(256) void gemm_tc(
    int mode_base, const float* __restrict__ b0, const float* __restrict__ b1,
    const float* __restrict__ b2, const float* __restrict__ b3,
    float* __restrict__ out)
{
#if HAS_TCGEN05
    extern __shared__ char sm[];
    const uint32_t smb = smem_u32(sm);
    const int tid = threadIdx.x;
    const int wid = tid >> 5;
    const int lid = tid & 31;
    const int rm = blockIdx.y;
    const int bx = blockIdx.x;
    const int mode = mode_base + blockIdx.z;

    const __nv_bfloat16* Ah = (mode < 3) ? g_xh : g_chh;
    const __nv_bfloat16* Al = (mode < 3) ? g_xl : g_cll;
    const __nv_bfloat16* Bh = g_wh[mode];
    const __nv_bfloat16* Bl = g_wl[mode];
    const float* bias = (mode == 0) ? b0 : (mode == 1) ? b1 : (mode == 2) ? b2 : b3;
    const float alpha = (mode == 0) ? 0.08838834764831845f : 1.0f;

    if (wid == 0) TCGEN05_ALLOC(smb + 0, 256);
    if (tid == 0) {
#pragma unroll
        for (int s = 0; s < 2; ++s) {
            MBARRIER_INIT(smb + 64 + 16 * s, 1);
            MBARRIER_INIT(smb + 96 + 16 * s, 1);
        }
    }
    __syncthreads();

    uint32_t tmem;
    asm volatile("ld.shared.b32 %0, [%1];" : "=r"(tmem) : "r"(smb + 0));

    if (wid == 0 && elect_one_pred()) {
#define LOAD_CHUNK(c, s)                                                        \
        do {                                                                    \
            uint32_t st = smb + SMB0 + (s) * STG;                               \
            uint32_t fb = smb + 64 + 16 * (s);                                  \
            size_t ao = ((size_t)((c) * NRT_A + rm)) << 14;                     \
            size_t bo = ((size_t)((c) * NRT_W + 2 * bx)) << 14;                 \
            MBARRIER_EXPECT_TX(fb, 6 * TIL);                                    \
            BULK_CP(st,           (const char*)Ah + ao, TIL,     fb);           \
            BULK_CP(st + TIL,     (const char*)Al + ao, TIL,     fb);           \
            BULK_CP(st + 2 * TIL, (const char*)Bh + bo, 2 * TIL, fb);           \
            BULK_CP(st + 4 * TIL, (const char*)Bl + bo, 2 * TIL, fb);           \
        } while (0)

        LOAD_CHUNK(0, 0);
        LOAD_CHUNK(1, 1);

        for (int c = 0; c < NCH; ++c) {
            int s = c & 1, ph = (c >> 1) & 1;
            uint32_t st = smb + SMB0 + s * STG;
            MBARRIER_WAIT_PARITY(smb + 64 + 16 * s, ph);
            uint64_t dAh = MAKE_SMEM_DESC(st);
            uint64_t dAl = MAKE_SMEM_DESC(st + TIL);
            uint64_t dBh = MAKE_SMEM_DESC(st + 2 * TIL);
            uint64_t dBl = MAKE_SMEM_DESC(st + 4 * TIL);
#pragma unroll
            for (int ks = 0; ks < 4; ++ks) {
                mma_f16_ss(tmem, dAh + ks * 2, dBh + ks * 2, GEMM_IDESC, (c | ks) != 0);
                mma_f16_ss(tmem, dAl + ks * 2, dBh + ks * 2, GEMM_IDESC, 1);
                mma_f16_ss(tmem, dAh + ks * 2, dBl + ks * 2, GEMM_IDESC, 1);
            }
            TCGEN05_COMMIT(smb + 96 + 16 * s);
            if (c + 2 < NCH) {
                MBARRIER_WAIT_PARITY(smb + 96 + 16 * s, ph);
                LOAD_CHUNK(c + 2, s);
            }
        }
        MBARRIER_WAIT_PARITY(smb + 96 + 16 * ((NCH - 1) & 1), ((NCH - 1) >> 1) & 1);
#undef LOAD_CHUNK
    }
    __syncthreads();
    TCGEN05_FENCE_AFTER();

    // epilogue: wg = col half (one head for modes<3), sub = row group
    const int wg = wid >> 2;
    const int sub = wid & 3;
    const int m = blockIdx.y * 128 + sub * 32 + lid;     // global token / row
    const int hd = bx * 2 + wg;                          // head (modes<3)
    const int b_ = m >> 11, s_ = m & 2047;
    const int bh2 = b_ * 16 + hd;
    __align__(16) __nv_bfloat16 hv[8], lv[8];

#pragma unroll
    for (int cb = 0; cb < 4; ++cb) {
        uint32_t r[32];
        TCGEN05_LD_32X32B_X32(r, tmem + wg * 128 + cb * 32);
        TCGEN05_WAIT_LD();
        int n0 = bx * 256 + wg * 128 + cb * 32;

        if (mode == 3) {
            float* crow = out + (size_t)m * D_MODEL;
#pragma unroll
            for (int j = 0; j < 32; j += 4) {
                float4 o;
                o.x = __uint_as_float(r[j + 0]) + bias[n0 + j + 0];
                o.y = __uint_as_float(r[j + 1]) + bias[n0 + j + 1];
                o.z = __uint_as_float(r[j + 2]) + bias[n0 + j + 2];
                o.w = __uint_as_float(r[j + 3]) + bias[n0 + j + 3];
                *(float4*)(crow + n0 + j) = o;
            }
        } else if (mode == 2) {
            float* crow = g_v + (size_t)m * D_MODEL;
#pragma unroll
            for (int j = 0; j < 32; j += 4) {
                float4 o;
                o.x = __uint_as_float(r[j + 0]) + bias[n0 + j + 0];
                o.y = __uint_as_float(r[j + 1]) + bias[n0 + j + 1];
                o.z = __uint_as_float(r[j + 2]) + bias[n0 + j + 2];
                o.w = __uint_as_float(r[j + 3]) + bias[n0 + j + 3];
                *(float4*)(crow + n0 + j) = o;
            }
        } else {
            // packed attention operand epilogue (Q: mode 0, K: mode 1)
            size_t tb;
            uint32_t rr;
            char *dh, *dl;
            if (mode == 0) {
                int rt2 = s_ >> 7; rr = s_ & 127;
                tb = ((size_t)((bh2 * 16 + rt2) * 2 + (cb >> 1))) << 14;
                dh = (char*)g_aqh + tb; dl = (char*)g_aql + tb;
            } else {
                int kt = s_ >> 6; rr = s_ & 63;
                tb = ((size_t)((bh2 * 32 + kt) * 2 + (cb >> 1))) << 13;
                dh = (char*)g_akh + tb; dl = (char*)g_akl + tb;
            }
            int kcb = (cb & 1) * 32;
#pragma unroll
            for (int j0 = 0; j0 < 32; j0 += 8) {
#pragma unroll
                for (int j = 0; j < 8; ++j) {
                    float f = (__uint_as_float(r[j0 + j]) + bias[n0 + j0 + j]) * alpha;
                    split_bf16(f, hv[j], lv[j]);
                }
                uint32_t so = SMEM_SWIZZLE_128B((uint32_t)(rr * 128 + (kcb + j0) * 2));
                *(uint4*)(dh + so) = *(uint4*)hv;
                *(uint4*)(dl + so) = *(uint4*)lv;
            }
        }
    }
    TCGEN05_FENCE_BEFORE();

    __syncthreads();
    if (tid == 0) {
#pragma unroll
        for (int s = 0; s < 2; ++s) {
            MBARRIER_INVAL(smb + 64 + 16 * s);
            MBARRIER_INVAL(smb + 96 + 16 * s);
        }
    }
    __syncthreads();
    if (wid == 0) {
        TCGEN05_RELINQUISH();
        TCGEN05_DEALLOC(tmem, 256);
    }
#endif
}

// ============================================================
// tcgen05 flash attention (R9 pipeline) + packed-ctx epilogue
// ============================================================
#define AOFF_MASK 1024
#define AOFF_K    9216              // 2 stages x 32KB (Kh|Kl)
#define AOFF_V    74752             // 4 stages x 32KB (Vh|Vl)
#define AOFF_QS   (AOFF_V + 65536)  // Q staging overlays V stages 2,3
#define ATTN_SMEM 205824
#define IDESC_S   0x8100490u
#define IDESC_PV  0x8200490u

__global__ __launch_bounds__(160) void attn_tc(const float* __restrict__ mask)
{
#if HAS_TCGEN05
    extern __shared__ char sm[];
    const uint32_t smb = smem_u32(sm);
    const int tid = threadIdx.x;
    const int wid = tid >> 5;
    const int lid = tid & 31;
    const int rt = blockIdx.x;
    const int bh = blockIdx.y;
    const int b = bh >> 4;

    if (wid == 0) TCGEN05_ALLOC(smb + 0, 512);
    if (tid == 0) {
        MBARRIER_INIT(smb + 64, 1);    // qbar (tx)
        MBARRIER_INIT(smb + 80, 4);    // qdone
#pragma unroll
        for (int s = 0; s < 2; ++s) {
            MBARRIER_INIT(smb + 96 + 16 * s, 1);    // full (tx)
            MBARRIER_INIT(smb + 128 + 16 * s, 1);   // s_full (commit)
            MBARRIER_INIT(smb + 160 + 16 * s, 4);   // smax_free
            MBARRIER_INIT(smb + 192 + 16 * s, 4);   // p_ready
            MBARRIER_INIT(smb + 224 + 16 * s, 1);   // pv_done (commit)
        }
    }
    for (int j = tid; j < SEQ; j += 160) {
        float mv = mask[b * SEQ + j];
        ((float*)(sm + AOFF_MASK))[j] = (1.0f - mv) * -1e30f;
    }
    __syncthreads();

    uint32_t tmem;
    asm volatile("ld.shared.b32 %0, [%1];" : "=r"(tmem) : "r"(smb + 0));

    // ---------------- control warp ----------------
    if (wid == 4) {
        if (elect_one_pred()) {
#define LOADKV(c)                                                          \
            do {                                                           \
                size_t kb = ((size_t)(bh * 32 + (c))) << 14;               \
                uint32_t kst = smb + AOFF_K + ((c) & 1) * 32768;           \
                uint32_t vst = smb + AOFF_V + ((c) & 3) * 32768;           \
                uint32_t fb = smb + 96 + 16 * ((c) & 1);                   \
                MBARRIER_EXPECT_TX(fb, 65536);                             \
                BULK_CP(kst,         (const char*)g_akh + kb, 16384, fb);  \
                BULK_CP(kst + 16384, (const char*)g_akl + kb, 16384, fb);  \
                BULK_CP(vst,         (const char*)g_avh + kb, 16384, fb);  \
                BULK_CP(vst + 16384, (const char*)g_avl + kb, 16384, fb);  \
            } while (0)

            {
                size_t qb = ((size_t)(bh * 16 + rt)) << 15;
                MBARRIER_EXPECT_TX(smb + 64, 65536);
                BULK_CP(smb + AOFF_QS,         (const char*)g_aqh + qb, 32768, smb + 64);
                BULK_CP(smb + AOFF_QS + 32768, (const char*)g_aql + qb, 32768, smb + 64);
                LOADKV(0);
                LOADKV(1);
            }
            MBARRIER_WAIT_PARITY(smb + 80, 0);
            TCGEN05_FENCE_AFTER();

            const uint32_t qh = tmem + 384, ql = tmem + 448;

            for (int i = 0; i < 32; ++i) {
                const int sb = i & 1;
                MBARRIER_WAIT_PARITY(smb + 96 + 16 * sb, (i >> 1) & 1);       // full
                if (i >= 2) MBARRIER_WAIT_PARITY(smb + 160 + 16 * sb, ((i - 2) >> 1) & 1);
                {
                    uint32_t kst = smb + AOFF_K + sb * 32768;
                    uint32_t sreg = tmem + sb * 64;
#pragma unroll
                    for (int st = 0; st < 8; ++st) {
                        uint64_t bh_ = MAKE_SMEM_DESC(kst + (st >> 2) * 8192) + (st & 3) * 2;
                        uint64_t bl_ = MAKE_SMEM_DESC(kst + 16384 + (st >> 2) * 8192) + (st & 3) * 2;
                        mma_f16_ts(sreg, qh + st * 8, bh_, IDESC_S, st != 0);
                        mma_f16_ts(sreg, ql + st * 8, bh_, IDESC_S, 1);
                        mma_f16_ts(sreg, qh + st * 8, bl_, IDESC_S, 1);
                    }
                    TCGEN05_COMMIT(smb + 128 + 16 * sb);
                }
                if (i >= 1) {
                    const int j = i - 1, pb = j & 1, pj = (j >> 1) & 1;
                    MBARRIER_WAIT_PARITY(smb + 192 + 16 * pb, pj);
                    TCGEN05_FENCE_AFTER();
                    uint32_t vst = smb + AOFF_V + (j & 3) * 32768;
                    uint64_t dVh = MAKE_SMEM_DESC(vst);
                    uint64_t dVl = MAKE_SMEM_DESC(vst + 16384);
#pragma unroll
                    for (int ks = 0; ks < 4; ++ks) {
                        uint32_t ah = tmem + 256 + pb * 64 + ks * 8;
                        uint32_t al = tmem + 288 + pb * 64 + ks * 8;
                        mma_f16_ts(tmem + 128, ah, dVh + ks * 2, IDESC_PV, (j | ks) != 0);
                        mma_f16_ts(tmem + 128, al, dVh + ks * 2, IDESC_PV, 1);
                        mma_f16_ts(tmem + 128, ah, dVl + ks * 2, IDESC_PV, 1);
                    }
                    TCGEN05_COMMIT(smb + 224 + 16 * pb);
                }
                if (i <= 29) {
                    MBARRIER_WAIT_PARITY(smb + 128 + 16 * sb, (i >> 1) & 1);  // s_full(i)
                    if (i >= 2)
                        MBARRIER_WAIT_PARITY(smb + 224 + 16 * (i & 1), ((i - 2) >> 1) & 1);
                    LOADKV(i + 2);
                }
            }
            {
                const int j = 31, pb = 1, pj = 1;
                MBARRIER_WAIT_PARITY(smb + 192 + 16 * pb, pj);
                TCGEN05_FENCE_AFTER();
                uint32_t vst = smb + AOFF_V + (j & 3) * 32768;
                uint64_t dVh = MAKE_SMEM_DESC(vst);
                uint64_t dVl = MAKE_SMEM_DESC(vst + 16384);
#pragma unroll
                for (int ks = 0; ks < 4; ++ks) {
                    uint32_t ah = tmem + 256 + pb * 64 + ks * 8;
                    uint32_t al = tmem + 288 + pb * 64 + ks * 8;
                    mma_f16_ts(tmem + 128, ah, dVh + ks * 2, IDESC_PV, 1);
                    mma_f16_ts(tmem + 128, al, dVh + ks * 2, IDESC_PV, 1);
                    mma_f16_ts(tmem + 128, ah, dVl + ks * 2, IDESC_PV, 1);
                }
                TCGEN05_COMMIT(smb + 224 + 16 * pb);
                MBARRIER_WAIT_PARITY(smb + 224 + 16 * pb, pj);
            }
#undef LOADKV
        }
    }

    // ---------------- softmax warps ----------------
    float l = 0.0f;
    if (wid < 4) {
        const uint32_t wo = (uint32_t)wid << 21;
        MBARRIER_WAIT_PARITY(smb + 64, 0);
        {
            const int r = wid * 32 + lid;
#pragma unroll
            for (int part = 0; part < 4; ++part) {
                uint32_t base = AOFF_QS + (part >> 1) * 32768 + (part & 1) * 16384;
                uint32_t q32[32];
#pragma unroll
                for (int g = 0; g < 8; ++g) {
                    uint32_t off = base + SMEM_SWIZZLE_128B((uint32_t)(r * 128 + g * 16));
                    uint4 v = *(const uint4*)(sm + off);
                    q32[g * 4 + 0] = v.x; q32[g * 4 + 1] = v.y;
                    q32[g * 4 + 2] = v.z; q32[g * 4 + 3] = v.w;
                }
                uint32_t dst = tmem + 384 + (part >> 1) * 64 + (part & 1) * 32 + wo;
                TCGEN05_ST_32X32B_X32(dst, q32);
            }
            TCGEN05_WAIT_ST();
            TCGEN05_FENCE_BEFORE();
            if (elect_one_pred()) MBARRIER_ARRIVE(smb + 80);   // qdone
        }

        const float* md_base = (const float*)(sm + AOFF_MASK);
        for (int i = 0; i < 32; ++i) {
            int s = i & 1, ph = (i >> 1) & 1;
            MBARRIER_WAIT_PARITY(smb + 128 + 16 * s, ph);      // s_full
            TCGEN05_FENCE_AFTER();
            uint32_t r0[32], r1[32];
            TCGEN05_LD_32X32B_X32(r0, tmem + s * 64);
            TCGEN05_LD_32X32B_X32(r1, tmem + s * 64 + 32);
            TCGEN05_WAIT_LD();
            if (elect_one_pred()) MBARRIER_ARRIVE(smb + 160 + 16 * s);  // smax_free

            const float* md = md_base + i * 64;
#pragma unroll
            for (int j = 0; j < 32; ++j) {
                float e = __expf(__uint_as_float(r0[j]) + md[j]);
                l += e;
                r0[j] = __float_as_uint(e);
            }
#pragma unroll
            for (int j = 0; j < 32; ++j) {
                float e = __expf(__uint_as_float(r1[j]) + md[32 + j]);
                l += e;
                r1[j] = __float_as_uint(e);
            }
            uint32_t phv[32], plv[32];
#pragma unroll
            for (int p = 0; p < 16; ++p) {
                __nv_bfloat16 h0, h1, l0, l1;
                split_bf16(__uint_as_float(r0[2 * p]), h0, l0);
                split_bf16(__uint_as_float(r0[2 * p + 1]), h1, l1);
                __nv_bfloat162 hp(h0, h1), lp(l0, l1);
                phv[p] = *(uint32_t*)&hp;
                plv[p] = *(uint32_t*)&lp;
            }
#pragma unroll
            for (int p = 0; p < 16; ++p) {
                __nv_bfloat16 h0, h1, l0, l1;
                split_bf16(__uint_as_float(r1[2 * p]), h0, l0);
                split_bf16(__uint_as_float(r1[2 * p + 1]), h1, l1);
                __nv_bfloat162 hp(h0, h1), lp(l0, l1);
                phv[16 + p] = *(uint32_t*)&hp;
                plv[16 + p] = *(uint32_t*)&lp;
            }
            TCGEN05_ST_32X32B_X32(tmem + 256 + s * 64 + wo, phv);
            TCGEN05_ST_32X32B_X32(tmem + 288 + s * 64 + wo, plv);
            TCGEN05_WAIT_ST();
            TCGEN05_FENCE_BEFORE();
            if (elect_one_pred()) MBARRIER_ARRIVE(smb + 192 + 16 * s);  // p_ready
        }
    }

    __syncthreads();

    // epilogue: normalize O and write PACKED ctx (O-proj A operand)
    if (wid < 4) {
        TCGEN05_FENCE_AFTER();
        float inv = 1.0f / l;
        int qrow = rt * 128 + wid * 32 + lid;
        int tok = b * 2048 + qrow;
        int rtt = tok >> 7, rr = tok & 127;
        int hh = bh & 15;
        __align__(16) __nv_bfloat16 hv[8], lv[8];
#pragma unroll
        for (int cb = 0; cb < 4; ++cb) {
            uint32_t r[32];
            TCGEN05_LD_32X32B_X32(r, tmem + 128 + cb * 32);
            TCGEN05_WAIT_LD();
            int c_ = hh * 2 + (cb >> 1);
            size_t tb = ((size_t)(c_ * NRT_A + rtt)) << 14;
            int kcb = (cb & 1) * 32;
#pragma unroll
            for (int j0 = 0; j0 < 32; j0 += 8) {
#pragma unroll
                for (int j = 0; j < 8; ++j)
                    split_bf16(__uint_as_float(r[j0 + j]) * inv, hv[j], lv[j]);
                uint32_t so = SMEM_SWIZZLE_128B((uint32_t)(rr * 128 + (kcb + j0) * 2));
                *(uint4*)((char*)g_chh + tb + so) = *(uint4*)hv;
                *(uint4*)((char*)g_cll + tb + so) = *(uint4*)lv;
            }
        }
        TCGEN05_FENCE_BEFORE();
    }

    __syncthreads();
    if (tid == 0) {
        MBARRIER_INVAL(smb + 64);
        MBARRIER_INVAL(smb + 80);
#pragma unroll
        for (int s = 0; s < 2; ++s) {
            MBARRIER_INVAL(smb + 96 + 16 * s);
            MBARRIER_INVAL(smb + 128 + 16 * s);
            MBARRIER_INVAL(smb + 160 + 16 * s);
            MBARRIER_INVAL(smb + 192 + 16 * s);
            MBARRIER_INVAL(smb + 224 + 16 * s);
        }
    }
    __syncthreads();
    if (wid == 0) {
        TCGEN05_RELINQUISH();
        TCGEN05_DEALLOC(tmem, 512);
    }
#endif  // HAS_TCGEN05
}

// ============================================================
extern "C" void kernel_launch(void* const* d_in, const int* in_sizes, int n_in,
                              void* d_out, int out_size)
{
    const float* x    = (const float*)d_in[0];
    const float* mask = (const float*)d_in[1];
    const float* Wq   = (const float*)d_in[2];
    const float* bq   = (const float*)d_in[3];
    const float* Wk   = (const float*)d_in[4];
    const float* bk   = (const float*)d_in[5];
    const float* Wv   = (const float*)d_in[6];
    const float* bv   = (const float*)d_in[7];
    const float* Wo   = (const float*)d_in[8];
    const float* bo   = (const float*)d_in[9];
    float* out = (float*)d_out;

    const int XN = M_TOK * D_MODEL;
    const int TOTAL8 = XN8 + 4 * WN8;

    cudaFuncSetAttribute(gemm_tc, cudaFuncAttributeMaxDynamicSharedMemorySize, GEMM_SMEM);
    cudaFuncSetAttribute(attn_tc, cudaFuncAttributeMaxDynamicSharedMemorySize, ATTN_SMEM);

    // 1. split + pack all GEMM operands (x + 4 weights)
    split_all<<<TOTAL8 / 256, 256>>>(x, Wq, Wk, Wv, Wo);

    // 2. QKV projections; Q/K epilogues pack attention operands, V -> fp32
    gemm_tc<<<dim3(8, 32, 3), 256, GEMM_SMEM>>>(0, bq, bk, bv, bo, out);

    // 3. V^T pack (scatter kernel)
    pack_v<<<XN / 8 / 256, 256>>>();

    // 4. attention (writes packed ctx)
    attn_tc<<<dim3(16, 32), 160, ATTN_SMEM>>>(mask);

    // 5. O projection -> output
    gemm_tc<<<dim3(8, 32, 1), 256, GEMM_SMEM>>>(3, bq, bk, bv, bo, out);
}